// round 6
// baseline (speedup 1.0000x reference)
#include <cuda_runtime.h>
#include <math.h>

// Problem constants
#define Bq 2
#define Hh 16
#define Tt 2048
#define Cc 1024
#define Dd 64
#define GK 1024   // K dim of both GEMMs

// Scratch (device globals: allocation-free)
__device__ float g_q[Bq*Hh*Tt*Dd];   // [B][H][T][64]
__device__ float g_k[Bq*Hh*Tt*Dd];
__device__ float g_v[Bq*Hh*Tt*Dd];
__device__ float g_o[Bq*Tt*Cc];      // [B][T][C], c = h*64+d

__device__ __forceinline__ float4 f4fma(float s, const float4 v, float4 a) {
    a.x = fmaf(s, v.x, a.x);
    a.y = fmaf(s, v.y, a.y);
    a.z = fmaf(s, v.z, a.z);
    a.w = fmaf(s, v.w, a.w);
    return a;
}
__device__ __forceinline__ float4 f4s(const float4 v, float s) {
    return make_float4(v.x*s, v.y*s, v.z*s, v.w*s);
}

// MODE 1 projection weight: reference views W_proj (1024x1024 row-major) as
// Wp[h, d, v] = W_flat[h*65536 + d*64 + v]  (h=k>>6, v=k&63, d=n).
// So the element for (n, k) lives at W_flat[(k>>6)*65536 + n*64 + (k&63)].
// Within a 4-aligned k-group, h is constant and v consecutive -> float4 OK.
__device__ __forceinline__ const float* wproj_addr(const float* __restrict__ W,
                                                   int n, int k) {
    return W + (((k >> 6) << 16) + (n << 6) + (k & 63));
}

// ---------------------------------------------------------------------------
// GEMM: out[m][n] = sum_k A[m][k] * W[n][k]     (A: Mx1024 row-major)
// MODE 0: A = x, W row-major [3072,1024], epilogue scatters q/k/v
// MODE 1: A = g_o, W = W_proj with the reshape-view indexing above,
//         epilogue writes dense out[m*1024+n]
// 128x128 tile, BK=8, 256 threads, 8x8 register tiles, gmem prefetch.
// ---------------------------------------------------------------------------
template<int MODE>
__global__ __launch_bounds__(256, 2)
void sgemm_kernel(const float* __restrict__ A,
                  const float* __restrict__ W,
                  float* __restrict__ out) {
    __shared__ float As[8][128];
    __shared__ float Bs[8][128];
    const float* Abase = (MODE == 1) ? (const float*)g_o : A;

    const int bm = blockIdx.y * 128;
    const int bn = blockIdx.x * 128;
    const int tid = threadIdx.x;
    const int tx = tid & 15;
    const int ty = tid >> 4;
    const int lrow = tid >> 1;
    const int lcol = (tid & 1) * 4;

    const float* Ald = Abase + (size_t)(bm + lrow) * GK + lcol;
    const int wn = bn + lrow;                 // weight row (output feature)

    float acc[8][8];
#pragma unroll
    for (int i = 0; i < 8; i++)
#pragma unroll
        for (int j = 0; j < 8; j++) acc[i][j] = 0.f;

    float4 pa = *(const float4*)(Ald);
    float4 pb;
    if (MODE == 0) pb = *(const float4*)(W + (size_t)wn * GK + lcol);
    else           pb = *(const float4*)wproj_addr(W, wn, lcol);

    for (int k0 = 0; k0 < GK; k0 += 8) {
        As[lcol+0][lrow] = pa.x;
        As[lcol+1][lrow] = pa.y;
        As[lcol+2][lrow] = pa.z;
        As[lcol+3][lrow] = pa.w;
        Bs[lcol+0][lrow] = pb.x;
        Bs[lcol+1][lrow] = pb.y;
        Bs[lcol+2][lrow] = pb.z;
        Bs[lcol+3][lrow] = pb.w;
        __syncthreads();
        if (k0 + 8 < GK) {
            pa = *(const float4*)(Ald + k0 + 8);
            int kk = k0 + 8 + lcol;
            if (MODE == 0) pb = *(const float4*)(W + (size_t)wn * GK + kk);
            else           pb = *(const float4*)wproj_addr(W, wn, kk);
        }
#pragma unroll
        for (int kk = 0; kk < 8; kk++) {
            float4 a0 = *(const float4*)&As[kk][ty*4];
            float4 a1 = *(const float4*)&As[kk][ty*4 + 64];
            float4 b0 = *(const float4*)&Bs[kk][tx*4];
            float4 b1 = *(const float4*)&Bs[kk][tx*4 + 64];
            float av[8] = {a0.x, a0.y, a0.z, a0.w, a1.x, a1.y, a1.z, a1.w};
            float bv[8] = {b0.x, b0.y, b0.z, b0.w, b1.x, b1.y, b1.z, b1.w};
#pragma unroll
            for (int i = 0; i < 8; i++)
#pragma unroll
                for (int j = 0; j < 8; j++)
                    acc[i][j] = fmaf(av[i], bv[j], acc[i][j]);
        }
        __syncthreads();
    }

#pragma unroll
    for (int i = 0; i < 8; i++) {
        int rl = (i < 4) ? (ty*4 + i) : (64 + ty*4 + (i - 4));
        int m = bm + rl;
#pragma unroll
        for (int jh = 0; jh < 2; jh++) {
            int cl = (jh == 0) ? (tx*4) : (64 + tx*4);
            int n = bn + cl;
            float4 v = make_float4(acc[i][jh*4+0], acc[i][jh*4+1],
                                   acc[i][jh*4+2], acc[i][jh*4+3]);
            if (MODE == 0) {
                int which = n >> 10;        // 0:q 1:k 2:v
                int c = n & 1023;
                int h = c >> 6;
                int d = c & 63;
                int bb = m >> 11;
                int t  = m & 2047;
                float* dst = (which == 0) ? g_q : (which == 1) ? g_k : g_v;
                *(float4*)&dst[((size_t)((bb*Hh + h)*Tt + t))*Dd + d] = v;
            } else {
                *(float4*)&out[(size_t)m * Cc + n] = v;
            }
        }
    }
}

// ---------------------------------------------------------------------------
// Causal flash attention, fp32. One CTA = 64 query rows of one (b,h).
// Computes S^T (St[j][i] = k_j . q_i) so every multi-lane smem access is on
// the contiguous dim -> no padding, no bank conflicts in hot loops.
// Dynamic smem: Qt[64][64] + Ks[64][64] + Vs[64][64] + St[64][64] + scl/l
// ---------------------------------------------------------------------------
__global__ __launch_bounds__(256, 2)
void attn_kernel() {
    extern __shared__ float smf[];
    float* Qt  = smf;           // Qt[d*64 + i]  (Q transposed)
    float* Ks  = smf + 4096;    // Ks[j*64 + d]
    float* Vs  = smf + 8192;    // Vs[j*64 + d]
    float* St  = smf + 12288;   // St[j*64 + i]
    float* scl = smf + 16384;   // [64] per-row rescale
    float* lsm = smf + 16448;   // [64] per-row l

    const int rb  = blockIdx.x;     // row block (0..31)
    const int bh  = blockIdx.y;     // b*16+h
    const int r0  = rb * 64;
    const int tid = threadIdx.x;

    const float* qb = g_q + (size_t)bh * (Tt * Dd);
    const float* kb = g_k + (size_t)bh * (Tt * Dd);
    const float* vb = g_v + (size_t)bh * (Tt * Dd);
    const int bb = bh >> 4, hh = bh & 15;
    float* ob = g_o + (size_t)bb * Tt * Cc + hh * Dd;

    // Load + transpose Q block (once per CTA)
    for (int idx = tid; idx < 1024; idx += 256) {
        int i = idx >> 4, c4 = idx & 15;
        float4 q4 = *(const float4*)(qb + (size_t)(r0 + i) * Dd + c4 * 4);
        int d0 = c4 * 4;
        Qt[(d0+0)*64 + i] = q4.x;
        Qt[(d0+1)*64 + i] = q4.y;
        Qt[(d0+2)*64 + i] = q4.z;
        Qt[(d0+3)*64 + i] = q4.w;
    }

    float m_run = -INFINITY, l_run = 0.f;   // valid in threads 0..63
    const int ig = tid >> 4, dg = tid & 15; // PV: rows 4ig..+3, cols 4dg..+3
    const int sx = dg, sy = ig;             // S: j rows 4sy..+3, i cols 4sx..+3
    float4 o0 = make_float4(0,0,0,0), o1 = o0, o2 = o0, o3 = o0;

    __syncthreads();

    for (int kv = 0; kv <= rb; kv++) {
        // Load K,V tile (coalesced, conflict-free float4 STS)
        for (int idx = tid; idx < 1024; idx += 256) {
            int j = idx >> 4, c4 = idx & 15;
            *(float4*)&Ks[j*64 + c4*4] =
                *(const float4*)(kb + (size_t)(kv*64 + j)*Dd + c4*4);
            *(float4*)&Vs[j*64 + c4*4] =
                *(const float4*)(vb + (size_t)(kv*64 + j)*Dd + c4*4);
        }
        __syncthreads();

        // S^T compute: St[j][i] = sum_d Ks[j][d] * Qt[d][i]; 4x4 reg tile
        {
            float4 c0 = make_float4(0,0,0,0), c1 = c0, c2 = c0, c3 = c0;
#pragma unroll
            for (int d4 = 0; d4 < 16; d4++) {
                float4 k0 = *(const float4*)&Ks[(sy*4+0)*64 + d4*4];
                float4 k1 = *(const float4*)&Ks[(sy*4+1)*64 + d4*4];
                float4 k2 = *(const float4*)&Ks[(sy*4+2)*64 + d4*4];
                float4 k3 = *(const float4*)&Ks[(sy*4+3)*64 + d4*4];
                float4 q0 = *(const float4*)&Qt[(d4*4+0)*64 + sx*4];
                float4 q1 = *(const float4*)&Qt[(d4*4+1)*64 + sx*4];
                float4 q2 = *(const float4*)&Qt[(d4*4+2)*64 + sx*4];
                float4 q3 = *(const float4*)&Qt[(d4*4+3)*64 + sx*4];
                c0 = f4fma(k0.x, q0, c0); c0 = f4fma(k0.y, q1, c0);
                c0 = f4fma(k0.z, q2, c0); c0 = f4fma(k0.w, q3, c0);
                c1 = f4fma(k1.x, q0, c1); c1 = f4fma(k1.y, q1, c1);
                c1 = f4fma(k1.z, q2, c1); c1 = f4fma(k1.w, q3, c1);
                c2 = f4fma(k2.x, q0, c2); c2 = f4fma(k2.y, q1, c2);
                c2 = f4fma(k2.z, q2, c2); c2 = f4fma(k2.w, q3, c2);
                c3 = f4fma(k3.x, q0, c3); c3 = f4fma(k3.y, q1, c3);
                c3 = f4fma(k3.z, q2, c3); c3 = f4fma(k3.w, q3, c3);
            }
            *(float4*)&St[(sy*4+0)*64 + sx*4] = c0;
            *(float4*)&St[(sy*4+1)*64 + sx*4] = c1;
            *(float4*)&St[(sy*4+2)*64 + sx*4] = c2;
            *(float4*)&St[(sy*4+3)*64 + sx*4] = c3;
        }
        __syncthreads();

        // Online softmax on 64 threads (one row each); m/l in registers
        if (tid < 64) {
            const int i = tid;
            const int jlim = (kv == rb) ? (i + 1) : 64;   // causal
            float mx = -INFINITY;
            for (int j = 0; j < jlim; j++) mx = fmaxf(mx, St[j*64 + i]);
            float m_new = fmaxf(m_run, mx);
            float sc = __expf(m_run - m_new);
            float sum = 0.f;
            for (int j = 0; j < jlim; j++) {
                float e = __expf(St[j*64 + i] - m_new);
                St[j*64 + i] = e;
                sum += e;
            }
            for (int j = jlim; j < 64; j++) St[j*64 + i] = 0.f;  // mask for PV
            l_run = fmaf(l_run, sc, sum);
            m_run = m_new;
            scl[i] = sc;
        }
        __syncthreads();

        // PV: O[i][d] += P[i][j] * V[j][d]; thread = 4 rows x 4 cols
        {
            float s0 = scl[ig*4+0], s1 = scl[ig*4+1];
            float s2 = scl[ig*4+2], s3 = scl[ig*4+3];
            o0 = f4s(o0, s0); o1 = f4s(o1, s1);
            o2 = f4s(o2, s2); o3 = f4s(o3, s3);
#pragma unroll 8
            for (int j = 0; j < 64; j++) {
                float4 p = *(const float4*)&St[j*64 + ig*4];
                float4 v = *(const float4*)&Vs[j*64 + dg*4];
                o0 = f4fma(p.x, v, o0);
                o1 = f4fma(p.y, v, o1);
                o2 = f4fma(p.z, v, o2);
                o3 = f4fma(p.w, v, o3);
            }
        }
        __syncthreads();   // protect Ks/Vs/St before next iteration's loads
    }

    if (tid < 64) lsm[tid] = l_run;
    __syncthreads();

    {
        float i0 = 1.f / lsm[ig*4+0];
        float i1 = 1.f / lsm[ig*4+1];
        float i2 = 1.f / lsm[ig*4+2];
        float i3 = 1.f / lsm[ig*4+3];
        *(float4*)&ob[(size_t)(r0 + ig*4+0)*Cc + dg*4] = f4s(o0, i0);
        *(float4*)&ob[(size_t)(r0 + ig*4+1)*Cc + dg*4] = f4s(o1, i1);
        *(float4*)&ob[(size_t)(r0 + ig*4+2)*Cc + dg*4] = f4s(o2, i2);
        *(float4*)&ob[(size_t)(r0 + ig*4+3)*Cc + dg*4] = f4s(o3, i3);
    }
}

// ---------------------------------------------------------------------------
extern "C" void kernel_launch(void* const* d_in, const int* in_sizes, int n_in,
                              void* d_out, int out_size) {
    const float* x  = (const float*)d_in[0];   // [2,2048,1024]
    const float* Wa = (const float*)d_in[1];   // [3072,1024]
    const float* Wp = (const float*)d_in[2];   // [1024,1024]
    float* y = (float*)d_out;                  // [2,2048,1024]

    // 66048 B dynamic smem for attention (host-side attribute set; not a
    // stream op, capture-safe, idempotent)
    cudaFuncSetAttribute((const void*)attn_kernel,
                         cudaFuncAttributeMaxDynamicSharedMemorySize, 66048);

    dim3 blk(256);
    // QKV: M=4096, N=3072
    sgemm_kernel<0><<<dim3(24, 32), blk>>>(x, Wa, nullptr);
    // Attention: grid (row blocks=32, b*h=32)
    attn_kernel<<<dim3(32, 32), blk, 66048>>>();
    // Proj: M=4096, N=1024
    sgemm_kernel<1><<<dim3(8, 32), blk>>>(nullptr, Wp, y);
}

// round 9
// speedup vs baseline: 1.3619x; 1.3619x over previous
#include <cuda_runtime.h>
#include <cuda_bf16.h>
#include <math.h>
#include <stdint.h>

// Problem constants
#define Bq 2
#define Hh 16
#define Tt 2048
#define Cc 1024
#define Dd 64
#define KP 3072     // packed K (3x1024) for bf16-split GEMMs
#define NCH 48      // K chunks of 64 bf16

// Scratch (device globals: allocation-free). 16B alignment for cp.async.
__device__ float g_q[Bq*Hh*Tt*Dd];
__device__ float g_k[Bq*Hh*Tt*Dd];
__device__ float g_v[Bq*Hh*Tt*Dd];
__device__ float g_o[Bq*Tt*Cc];
__device__ __align__(16) __nv_bfloat16 g_ax[4096*KP];  // packed x      [hi|hi|lo]
__device__ __align__(16) __nv_bfloat16 g_wa[3072*KP];  // packed W_attn [hi|lo|hi]
__device__ __align__(16) __nv_bfloat16 g_wp[1024*KP];  // packed W_proj(view) [hi|lo|hi]
__device__ __align__(16) __nv_bfloat16 g_ox[4096*KP];  // packed O      [hi|hi|lo]

// ---------------------------------------------------------------------------
// Baseline-ISA helpers (sm_80+; valid on plain sm_103 target)
// ---------------------------------------------------------------------------
static __device__ __forceinline__ uint32_t s2u(const void* p) {
    uint32_t a;
    asm("{ .reg .u64 t; cvta.to.shared.u64 t, %1; cvt.u32.u64 %0, t; }"
        : "=r"(a) : "l"(p));
    return a;
}
#define SWZ(o) ((o) ^ (((o) >> 3) & 0x70))

static __device__ __forceinline__ void mma16816(float* c, const uint32_t* a,
                                                const uint32_t* b) {
    asm volatile(
        "mma.sync.aligned.m16n8k16.row.col.f32.bf16.bf16.f32 "
        "{%0,%1,%2,%3}, {%4,%5,%6,%7}, {%8,%9}, {%0,%1,%2,%3};"
        : "+f"(c[0]), "+f"(c[1]), "+f"(c[2]), "+f"(c[3])
        : "r"(a[0]), "r"(a[1]), "r"(a[2]), "r"(a[3]), "r"(b[0]), "r"(b[1]));
}
static __device__ __forceinline__ void ldsm4(uint32_t* r, uint32_t addr) {
    asm volatile("ldmatrix.sync.aligned.m8n8.x4.shared.b16 {%0,%1,%2,%3}, [%4];"
                 : "=r"(r[0]), "=r"(r[1]), "=r"(r[2]), "=r"(r[3]) : "r"(addr));
}
static __device__ __forceinline__ void cp16(uint32_t dst, const void* src) {
    asm volatile("cp.async.cg.shared.global [%0], [%1], 16;" :: "r"(dst), "l"(src));
}
#define CP_COMMIT() asm volatile("cp.async.commit_group;" ::: "memory")
#define CP_WAIT1()  asm volatile("cp.async.wait_group 1;" ::: "memory")

// ---------------------------------------------------------------------------
// Pack kernels: one block per row, 256 threads, each thread 4 elems.
// hi = bf16(a), lo = bf16(a - hi).  Activations [hi|hi|lo], weights [hi|lo|hi].
// KIND 0: x -> g_ax   KIND 1: W_attn -> g_wa
// KIND 2: W_proj(view) -> g_wp      KIND 3: g_o -> g_ox
// ---------------------------------------------------------------------------
template<int KIND>
__global__ __launch_bounds__(256)
void packk(const float* __restrict__ src) {
    const int m = blockIdx.x;
    const int c4 = threadIdx.x * 4;
    const float* sp;
    __nv_bfloat16* dst;
    if (KIND == 0)      { sp = src + (size_t)m * 1024 + c4; dst = g_ax; }
    else if (KIND == 1) { sp = src + (size_t)m * 1024 + c4; dst = g_wa; }
    else if (KIND == 2) { sp = src + (((c4 >> 6) << 16) + (m << 6) + (c4 & 63)); dst = g_wp; }
    else                { sp = (const float*)g_o + (size_t)m * 1024 + c4; dst = g_ox; }

    float4 v = *(const float4*)sp;
    float vv[4] = {v.x, v.y, v.z, v.w};
    union U { __nv_bfloat16 b[4]; uint2 u; };
    U H, L;
#pragma unroll
    for (int j = 0; j < 4; j++) {
        H.b[j] = __float2bfloat16(vv[j]);
        L.b[j] = __float2bfloat16(vv[j] - __bfloat162float(H.b[j]));
    }
    __nv_bfloat16* row = dst + (size_t)m * KP;
    *(uint2*)(row + c4) = H.u;
    if (KIND == 0 || KIND == 3) {
        *(uint2*)(row + 1024 + c4) = H.u;
        *(uint2*)(row + 2048 + c4) = L.u;
    } else {
        *(uint2*)(row + 1024 + c4) = L.u;
        *(uint2*)(row + 2048 + c4) = H.u;
    }
}

// ---------------------------------------------------------------------------
// bf16 mma.sync GEMM: D[m][n] = sum_k A'[m][k] * W'[n][k], K'=3072.
// 128x128 tile, BK=64 (SW128 rows), 2-stage cp.async, 8 warps (warp 32x64).
// MODE 0: A=g_ax, W=g_wa, epilogue scatters q/k/v
// MODE 1: A=g_ox, W=g_wp, epilogue writes out
// ---------------------------------------------------------------------------
template<int MODE>
__global__ __launch_bounds__(256, 2)
void gemmmma(float* __restrict__ out) {
    extern __shared__ __align__(1024) char sm[];
    const uint32_t smb = s2u(sm);
    const int tid = threadIdx.x, wid = tid >> 5, lane = tid & 31;
    const int bm = blockIdx.y * 128, bn = blockIdx.x * 128;
    const int wm = (wid & 3) * 32, wn = (wid >> 2) * 64;

    const __nv_bfloat16* __restrict__ A = MODE ? g_ox : g_ax;
    const __nv_bfloat16* __restrict__ W = MODE ? g_wp : g_wa;

    // stage s: A at smb + s*16384, B at smb + 32768 + s*16384 (16KB tiles)
    auto load = [&](int c, int s) {
        const __nv_bfloat16* Ab = A + (size_t)bm * KP + c * 64;
        const __nv_bfloat16* Wb = W + (size_t)bn * KP + c * 64;
        uint32_t as = smb + s * 16384;
        uint32_t bs = smb + 32768 + s * 16384;
#pragma unroll
        for (int t = 0; t < 4; t++) {
            int idx = tid + t * 256;            // 1024 16B chunks per tile
            int row = idx >> 3, col = idx & 7;
            uint32_t so = SWZ(row * 128 + col * 16);
            cp16(as + so, Ab + (size_t)row * KP + col * 8);
            cp16(bs + so, Wb + (size_t)row * KP + col * 8);
        }
    };

    float acc[2][8][4];
#pragma unroll
    for (int i = 0; i < 2; i++)
#pragma unroll
        for (int j = 0; j < 8; j++)
#pragma unroll
            for (int q = 0; q < 4; q++) acc[i][j][q] = 0.f;

    load(0, 0); CP_COMMIT();
    load(1, 1); CP_COMMIT();

    for (int c = 0; c < NCH; c++) {
        CP_WAIT1();
        __syncthreads();
        const uint32_t ab = smb + (c & 1) * 16384;
        const uint32_t bb = smb + 32768 + (c & 1) * 16384;
#pragma unroll
        for (int k16 = 0; k16 < 4; k16++) {
            const int colb = k16 * 32 + (lane >> 4) * 16;
            uint32_t a[2][4], b4[4][4];
#pragma unroll
            for (int mt = 0; mt < 2; mt++) {
                int row = wm + mt * 16 + (lane & 15);
                ldsm4(a[mt], ab + SWZ(row * 128 + colb));
            }
#pragma unroll
            for (int nt2 = 0; nt2 < 4; nt2++) {
                int row = wn + nt2 * 16 + (lane & 15);
                ldsm4(b4[nt2], bb + SWZ(row * 128 + colb));
            }
#pragma unroll
            for (int mt = 0; mt < 2; mt++)
#pragma unroll
                for (int nt2 = 0; nt2 < 4; nt2++) {
                    uint32_t b0[2] = {b4[nt2][0], b4[nt2][2]};  // n tile 2*nt2
                    uint32_t b1[2] = {b4[nt2][1], b4[nt2][3]};  // n tile 2*nt2+1
                    mma16816(acc[mt][nt2 * 2 + 0], a[mt], b0);
                    mma16816(acc[mt][nt2 * 2 + 1], a[mt], b1);
                }
        }
        __syncthreads();
        if (c + 2 < NCH) load(c + 2, c & 1);
        CP_COMMIT();
    }

    // Epilogue: c-fragment thread t holds rows r4/r4+8, cols c2,c2+1
    const int r4 = lane >> 2, c2 = (lane & 3) * 2;
#pragma unroll
    for (int mt = 0; mt < 2; mt++) {
#pragma unroll
        for (int nt = 0; nt < 8; nt++) {
            const int m0 = bm + wm + mt * 16 + r4;
            const int n  = bn + wn + nt * 8 + c2;
            float2 v0 = make_float2(acc[mt][nt][0], acc[mt][nt][1]);
            float2 v1 = make_float2(acc[mt][nt][2], acc[mt][nt][3]);
            if (MODE == 0) {
                const int which = n >> 10, cc = n & 1023;
                const int h = cc >> 6, d = cc & 63;
                const int b = m0 >> 11, t0 = m0 & 2047;
                float* dst = (which == 0) ? g_q : (which == 1) ? g_k : g_v;
                const size_t base = (size_t)(b * Hh + h) * Tt;
                *(float2*)&dst[(base + t0) * Dd + d] = v0;
                *(float2*)&dst[(base + t0 + 8) * Dd + d] = v1;
            } else {
                *(float2*)&out[(size_t)m0 * Cc + n] = v0;
                *(float2*)&out[(size_t)(m0 + 8) * Cc + n] = v1;
            }
        }
    }
}

// ---------------------------------------------------------------------------
// Causal flash attention, fp32 (unchanged; heavy tiles launched first)
// ---------------------------------------------------------------------------
__device__ __forceinline__ float4 f4fma(float s, const float4 v, float4 a) {
    a.x = fmaf(s, v.x, a.x); a.y = fmaf(s, v.y, a.y);
    a.z = fmaf(s, v.z, a.z); a.w = fmaf(s, v.w, a.w);
    return a;
}
__device__ __forceinline__ float4 f4s(const float4 v, float s) {
    return make_float4(v.x*s, v.y*s, v.z*s, v.w*s);
}

__global__ __launch_bounds__(256, 2)
void attn_kernel() {
    extern __shared__ float smf[];
    float* Qt  = smf;
    float* Ks  = smf + 4096;
    float* Vs  = smf + 8192;
    float* St  = smf + 12288;
    float* scl = smf + 16384;
    float* lsm = smf + 16448;

    const int rb  = (int)(gridDim.x - 1) - (int)blockIdx.x;  // heavy first
    const int bh  = blockIdx.y;
    const int r0  = rb * 64;
    const int tid = threadIdx.x;

    const float* qb = g_q + (size_t)bh * (Tt * Dd);
    const float* kb = g_k + (size_t)bh * (Tt * Dd);
    const float* vb = g_v + (size_t)bh * (Tt * Dd);
    const int bb = bh >> 4, hh = bh & 15;
    float* ob = g_o + (size_t)bb * Tt * Cc + hh * Dd;

    for (int idx = tid; idx < 1024; idx += 256) {
        int i = idx >> 4, c4 = idx & 15;
        float4 q4 = *(const float4*)(qb + (size_t)(r0 + i) * Dd + c4 * 4);
        int d0 = c4 * 4;
        Qt[(d0+0)*64 + i] = q4.x;
        Qt[(d0+1)*64 + i] = q4.y;
        Qt[(d0+2)*64 + i] = q4.z;
        Qt[(d0+3)*64 + i] = q4.w;
    }

    float m_run = -INFINITY, l_run = 0.f;
    const int ig = tid >> 4, dg = tid & 15;
    const int sx = dg, sy = ig;
    float4 o0 = make_float4(0,0,0,0), o1 = o0, o2 = o0, o3 = o0;

    __syncthreads();

    for (int kv = 0; kv <= rb; kv++) {
        for (int idx = tid; idx < 1024; idx += 256) {
            int j = idx >> 4, c4 = idx & 15;
            *(float4*)&Ks[j*64 + c4*4] =
                *(const float4*)(kb + (size_t)(kv*64 + j)*Dd + c4*4);
            *(float4*)&Vs[j*64 + c4*4] =
                *(const float4*)(vb + (size_t)(kv*64 + j)*Dd + c4*4);
        }
        __syncthreads();

        {
            float4 c0 = make_float4(0,0,0,0), c1 = c0, c2 = c0, c3 = c0;
#pragma unroll
            for (int d4 = 0; d4 < 16; d4++) {
                float4 k0 = *(const float4*)&Ks[(sy*4+0)*64 + d4*4];
                float4 k1 = *(const float4*)&Ks[(sy*4+1)*64 + d4*4];
                float4 k2 = *(const float4*)&Ks[(sy*4+2)*64 + d4*4];
                float4 k3 = *(const float4*)&Ks[(sy*4+3)*64 + d4*4];
                float4 q0 = *(const float4*)&Qt[(d4*4+0)*64 + sx*4];
                float4 q1 = *(const float4*)&Qt[(d4*4+1)*64 + sx*4];
                float4 q2 = *(const float4*)&Qt[(d4*4+2)*64 + sx*4];
                float4 q3 = *(const float4*)&Qt[(d4*4+3)*64 + sx*4];
                c0 = f4fma(k0.x, q0, c0); c0 = f4fma(k0.y, q1, c0);
                c0 = f4fma(k0.z, q2, c0); c0 = f4fma(k0.w, q3, c0);
                c1 = f4fma(k1.x, q0, c1); c1 = f4fma(k1.y, q1, c1);
                c1 = f4fma(k1.z, q2, c1); c1 = f4fma(k1.w, q3, c1);
                c2 = f4fma(k2.x, q0, c2); c2 = f4fma(k2.y, q1, c2);
                c2 = f4fma(k2.z, q2, c2); c2 = f4fma(k2.w, q3, c2);
                c3 = f4fma(k3.x, q0, c3); c3 = f4fma(k3.y, q1, c3);
                c3 = f4fma(k3.z, q2, c3); c3 = f4fma(k3.w, q3, c3);
            }
            *(float4*)&St[(sy*4+0)*64 + sx*4] = c0;
            *(float4*)&St[(sy*4+1)*64 + sx*4] = c1;
            *(float4*)&St[(sy*4+2)*64 + sx*4] = c2;
            *(float4*)&St[(sy*4+3)*64 + sx*4] = c3;
        }
        __syncthreads();

        if (tid < 64) {
            const int i = tid;
            const int jlim = (kv == rb) ? (i + 1) : 64;
            float mx = -INFINITY;
            for (int j = 0; j < jlim; j++) mx = fmaxf(mx, St[j*64 + i]);
            float m_new = fmaxf(m_run, mx);
            float sc = __expf(m_run - m_new);
            float sum = 0.f;
            for (int j = 0; j < jlim; j++) {
                float e = __expf(St[j*64 + i] - m_new);
                St[j*64 + i] = e;
                sum += e;
            }
            for (int j = jlim; j < 64; j++) St[j*64 + i] = 0.f;
            l_run = fmaf(l_run, sc, sum);
            m_run = m_new;
            scl[i] = sc;
        }
        __syncthreads();

        {
            float s0 = scl[ig*4+0], s1 = scl[ig*4+1];
            float s2 = scl[ig*4+2], s3 = scl[ig*4+3];
            o0 = f4s(o0, s0); o1 = f4s(o1, s1);
            o2 = f4s(o2, s2); o3 = f4s(o3, s3);
#pragma unroll 8
            for (int j = 0; j < 64; j++) {
                float4 p = *(const float4*)&St[j*64 + ig*4];
                float4 v = *(const float4*)&Vs[j*64 + dg*4];
                o0 = f4fma(p.x, v, o0);
                o1 = f4fma(p.y, v, o1);
                o2 = f4fma(p.z, v, o2);
                o3 = f4fma(p.w, v, o3);
            }
        }
        __syncthreads();
    }

    if (tid < 64) lsm[tid] = l_run;
    __syncthreads();

    {
        float i0 = 1.f / lsm[ig*4+0];
        float i1 = 1.f / lsm[ig*4+1];
        float i2 = 1.f / lsm[ig*4+2];
        float i3 = 1.f / lsm[ig*4+3];
        *(float4*)&ob[(size_t)(r0 + ig*4+0)*Cc + dg*4] = f4s(o0, i0);
        *(float4*)&ob[(size_t)(r0 + ig*4+1)*Cc + dg*4] = f4s(o1, i1);
        *(float4*)&ob[(size_t)(r0 + ig*4+2)*Cc + dg*4] = f4s(o2, i2);
        *(float4*)&ob[(size_t)(r0 + ig*4+3)*Cc + dg*4] = f4s(o3, i3);
    }
}

// ---------------------------------------------------------------------------
extern "C" void kernel_launch(void* const* d_in, const int* in_sizes, int n_in,
                              void* d_out, int out_size) {
    const float* x  = (const float*)d_in[0];   // [2,2048,1024]
    const float* Wa = (const float*)d_in[1];   // [3072,1024]
    const float* Wp = (const float*)d_in[2];   // [1024,1024]
    float* y = (float*)d_out;                  // [2,2048,1024]

    static const int GSM = 65536;              // 2 stages x (16KB A + 16KB B)
    cudaFuncSetAttribute((const void*)gemmmma<0>,
                         cudaFuncAttributeMaxDynamicSharedMemorySize, GSM);
    cudaFuncSetAttribute((const void*)gemmmma<1>,
                         cudaFuncAttributeMaxDynamicSharedMemorySize, GSM);
    cudaFuncSetAttribute((const void*)attn_kernel,
                         cudaFuncAttributeMaxDynamicSharedMemorySize, 66048);

    packk<0><<<4096, 256>>>(x);
    packk<1><<<3072, 256>>>(Wa);
    packk<2><<<1024, 256>>>(Wp);

    gemmmma<0><<<dim3(24, 32), 256, GSM>>>(nullptr);   // QKV (N=3072)

    attn_kernel<<<dim3(32, 32), 256, 66048>>>();

    packk<3><<<4096, 256>>>(nullptr);

    gemmmma<1><<<dim3(8, 32), 256, GSM>>>(y);          // proj (N=1024)
}

// round 10
// speedup vs baseline: 1.9819x; 1.4552x over previous
#include <cuda_runtime.h>
#include <cuda_bf16.h>
#include <math.h>
#include <stdint.h>

// Problem constants
#define Bq 2
#define Hh 16
#define Tt 2048
#define Cc 1024
#define Dd 64
#define KP 3072     // packed K (3x1024) for bf16-split GEMMs
#define NCH 48      // K chunks of 64 bf16

// Scratch (device globals: allocation-free). 16B alignment for cp.async.
__device__ float g_q[Bq*Hh*Tt*Dd];
__device__ float g_k[Bq*Hh*Tt*Dd];
__device__ float g_v[Bq*Hh*Tt*Dd];
__device__ float g_o[Bq*Tt*Cc];
__device__ __align__(16) __nv_bfloat16 g_ax[4096*KP];  // packed x      [hi|hi|lo]
__device__ __align__(16) __nv_bfloat16 g_wa[3072*KP];  // packed W_attn [hi|lo|hi]
__device__ __align__(16) __nv_bfloat16 g_wp[1024*KP];  // packed W_proj(view) [hi|lo|hi]
__device__ __align__(16) __nv_bfloat16 g_ox[4096*KP];  // packed O      [hi|hi|lo]

// ---------------------------------------------------------------------------
// Baseline-ISA helpers (sm_80+; valid on plain sm_103 target)
// ---------------------------------------------------------------------------
static __device__ __forceinline__ uint32_t s2u(const void* p) {
    uint32_t a;
    asm("{ .reg .u64 t; cvta.to.shared.u64 t, %1; cvt.u32.u64 %0, t; }"
        : "=r"(a) : "l"(p));
    return a;
}
#define SWZ(o) ((o) ^ (((o) >> 3) & 0x70))

static __device__ __forceinline__ void mma16816(float* c, const uint32_t* a,
                                                const uint32_t* b) {
    asm volatile(
        "mma.sync.aligned.m16n8k16.row.col.f32.bf16.bf16.f32 "
        "{%0,%1,%2,%3}, {%4,%5,%6,%7}, {%8,%9}, {%0,%1,%2,%3};"
        : "+f"(c[0]), "+f"(c[1]), "+f"(c[2]), "+f"(c[3])
        : "r"(a[0]), "r"(a[1]), "r"(a[2]), "r"(a[3]), "r"(b[0]), "r"(b[1]));
}
static __device__ __forceinline__ void ldsm4(uint32_t* r, uint32_t addr) {
    asm volatile("ldmatrix.sync.aligned.m8n8.x4.shared.b16 {%0,%1,%2,%3}, [%4];"
                 : "=r"(r[0]), "=r"(r[1]), "=r"(r[2]), "=r"(r[3]) : "r"(addr));
}
static __device__ __forceinline__ void ldsm4t(uint32_t* r, uint32_t addr) {
    asm volatile("ldmatrix.sync.aligned.m8n8.x4.trans.shared.b16 {%0,%1,%2,%3}, [%4];"
                 : "=r"(r[0]), "=r"(r[1]), "=r"(r[2]), "=r"(r[3]) : "r"(addr));
}
static __device__ __forceinline__ void cp16(uint32_t dst, const void* src) {
    asm volatile("cp.async.cg.shared.global [%0], [%1], 16;" :: "r"(dst), "l"(src));
}
#define CP_COMMIT() asm volatile("cp.async.commit_group;" ::: "memory")
#define CP_WAIT1()  asm volatile("cp.async.wait_group 1;" ::: "memory")

static __device__ __forceinline__ void st32(uint32_t a, uint32_t v) {
    asm volatile("st.shared.b32 [%0], %1;" :: "r"(a), "r"(v) : "memory");
}
static __device__ __forceinline__ uint32_t pk2(float a, float b) {
    __nv_bfloat162 t = __floats2bfloat162_rn(a, b);
    return *reinterpret_cast<uint32_t*>(&t);
}
static __device__ __forceinline__ float bhi(float x) {
    return __bfloat162float(__float2bfloat16(x));
}

// e^x for x <= 0 via FMA-pipe poly (no MUFU). err ~2.4e-6 rel.
static __device__ __forceinline__ float expapx(float x) {
    float y = fmaxf(x, -87.0f) * 1.44269504f;
    float z = y + 12582912.0f;          // round-to-nearest int (magic)
    float r = z - 12582912.0f;
    float f = y - r;                    // f in [-0.5, 0.5]
    float p = 1.33335581e-3f;
    p = fmaf(p, f, 9.61812911e-3f);
    p = fmaf(p, f, 5.55041087e-2f);
    p = fmaf(p, f, 2.40226507e-1f);
    p = fmaf(p, f, 6.93147181e-1f);
    p = fmaf(p, f, 1.0f);
    return p * __int_as_float((__float_as_int(z) << 23) + 0x3F800000);
}

// convert 16 fp32 -> bf16 hi/lo tiles (swizzled 128B rows)
static __device__ __forceinline__ void cvt16(uint32_t hb, uint32_t lb, int row,
                                             int d0, const float* src) {
#pragma unroll
    for (int p = 0; p < 4; p++) {
        float4 v = *(const float4*)(src + p * 4);
        uint32_t sw = SWZ((uint32_t)(row * 128 + (d0 + p * 4) * 2));
        st32(hb + sw,     pk2(v.x, v.y));
        st32(hb + sw + 4, pk2(v.z, v.w));
        st32(lb + sw,     pk2(v.x - bhi(v.x), v.y - bhi(v.y)));
        st32(lb + sw + 4, pk2(v.z - bhi(v.z), v.w - bhi(v.w)));
    }
}

// ---------------------------------------------------------------------------
// Pack kernels (unchanged from R9)
// ---------------------------------------------------------------------------
template<int KIND>
__global__ __launch_bounds__(256)
void packk(const float* __restrict__ src) {
    const int m = blockIdx.x;
    const int c4 = threadIdx.x * 4;
    const float* sp;
    __nv_bfloat16* dst;
    if (KIND == 0)      { sp = src + (size_t)m * 1024 + c4; dst = g_ax; }
    else if (KIND == 1) { sp = src + (size_t)m * 1024 + c4; dst = g_wa; }
    else if (KIND == 2) { sp = src + (((c4 >> 6) << 16) + (m << 6) + (c4 & 63)); dst = g_wp; }
    else                { sp = (const float*)g_o + (size_t)m * 1024 + c4; dst = g_ox; }

    float4 v = *(const float4*)sp;
    float vv[4] = {v.x, v.y, v.z, v.w};
    union U { __nv_bfloat16 b[4]; uint2 u; };
    U H, L;
#pragma unroll
    for (int j = 0; j < 4; j++) {
        H.b[j] = __float2bfloat16(vv[j]);
        L.b[j] = __float2bfloat16(vv[j] - __bfloat162float(H.b[j]));
    }
    __nv_bfloat16* row = dst + (size_t)m * KP;
    *(uint2*)(row + c4) = H.u;
    if (KIND == 0 || KIND == 3) {
        *(uint2*)(row + 1024 + c4) = H.u;
        *(uint2*)(row + 2048 + c4) = L.u;
    } else {
        *(uint2*)(row + 1024 + c4) = L.u;
        *(uint2*)(row + 2048 + c4) = H.u;
    }
}

// ---------------------------------------------------------------------------
// bf16 mma.sync GEMM (unchanged from R9)
// ---------------------------------------------------------------------------
template<int MODE>
__global__ __launch_bounds__(256, 2)
void gemmmma(float* __restrict__ out) {
    extern __shared__ __align__(1024) char sm[];
    const uint32_t smb = s2u(sm);
    const int tid = threadIdx.x, wid = tid >> 5, lane = tid & 31;
    const int bm = blockIdx.y * 128, bn = blockIdx.x * 128;
    const int wm = (wid & 3) * 32, wn = (wid >> 2) * 64;

    const __nv_bfloat16* __restrict__ A = MODE ? g_ox : g_ax;
    const __nv_bfloat16* __restrict__ W = MODE ? g_wp : g_wa;

    auto load = [&](int c, int s) {
        const __nv_bfloat16* Ab = A + (size_t)bm * KP + c * 64;
        const __nv_bfloat16* Wb = W + (size_t)bn * KP + c * 64;
        uint32_t as = smb + s * 16384;
        uint32_t bs = smb + 32768 + s * 16384;
#pragma unroll
        for (int t = 0; t < 4; t++) {
            int idx = tid + t * 256;
            int row = idx >> 3, col = idx & 7;
            uint32_t so = SWZ(row * 128 + col * 16);
            cp16(as + so, Ab + (size_t)row * KP + col * 8);
            cp16(bs + so, Wb + (size_t)row * KP + col * 8);
        }
    };

    float acc[2][8][4];
#pragma unroll
    for (int i = 0; i < 2; i++)
#pragma unroll
        for (int j = 0; j < 8; j++)
#pragma unroll
            for (int q = 0; q < 4; q++) acc[i][j][q] = 0.f;

    load(0, 0); CP_COMMIT();
    load(1, 1); CP_COMMIT();

    for (int c = 0; c < NCH; c++) {
        CP_WAIT1();
        __syncthreads();
        const uint32_t ab = smb + (c & 1) * 16384;
        const uint32_t bb = smb + 32768 + (c & 1) * 16384;
#pragma unroll
        for (int k16 = 0; k16 < 4; k16++) {
            const int colb = k16 * 32 + (lane >> 4) * 16;
            uint32_t a[2][4], b4[4][4];
#pragma unroll
            for (int mt = 0; mt < 2; mt++) {
                int row = wm + mt * 16 + (lane & 15);
                ldsm4(a[mt], ab + SWZ(row * 128 + colb));
            }
#pragma unroll
            for (int nt2 = 0; nt2 < 4; nt2++) {
                int row = wn + nt2 * 16 + (lane & 15);
                ldsm4(b4[nt2], bb + SWZ(row * 128 + colb));
            }
#pragma unroll
            for (int mt = 0; mt < 2; mt++)
#pragma unroll
                for (int nt2 = 0; nt2 < 4; nt2++) {
                    uint32_t b0[2] = {b4[nt2][0], b4[nt2][2]};
                    uint32_t b1[2] = {b4[nt2][1], b4[nt2][3]};
                    mma16816(acc[mt][nt2 * 2 + 0], a[mt], b0);
                    mma16816(acc[mt][nt2 * 2 + 1], a[mt], b1);
                }
        }
        __syncthreads();
        if (c + 2 < NCH) load(c + 2, c & 1);
        CP_COMMIT();
    }

    const int r4 = lane >> 2, c2 = (lane & 3) * 2;
#pragma unroll
    for (int mt = 0; mt < 2; mt++) {
#pragma unroll
        for (int nt = 0; nt < 8; nt++) {
            const int m0 = bm + wm + mt * 16 + r4;
            const int n  = bn + wn + nt * 8 + c2;
            float2 v0 = make_float2(acc[mt][nt][0], acc[mt][nt][1]);
            float2 v1 = make_float2(acc[mt][nt][2], acc[mt][nt][3]);
            if (MODE == 0) {
                const int which = n >> 10, cc = n & 1023;
                const int h = cc >> 6, d = cc & 63;
                const int b = m0 >> 11, t0 = m0 & 2047;
                float* dst = (which == 0) ? g_q : (which == 1) ? g_k : g_v;
                const size_t base = (size_t)(b * Hh + h) * Tt;
                *(float2*)&dst[(base + t0) * Dd + d] = v0;
                *(float2*)&dst[(base + t0 + 8) * Dd + d] = v1;
            } else {
                *(float2*)&out[(size_t)m0 * Cc + n] = v0;
                *(float2*)&out[(size_t)(m0 + 8) * Cc + n] = v1;
            }
        }
    }
}

// ---------------------------------------------------------------------------
// Tensor-core causal flash attention (bf16 hi/lo split, poly exp).
// CTA = 64 q-rows of one (b,h); 256 threads, 8 warps.
// Warp w: m-tile (w&3)*16 rows, n-half (w>>2)*32 cols for S and O.
// Smem bytes: QH 0, QL 8192, KH 16384, KL 24576, VH 32768, VL 40960,
//             PH 49152, PL 57344, S(fp32,stride 68) 65536..82944,
//             pm 82944, ps 83968, scl 84992, lsm 85248. Total 85504.
// ---------------------------------------------------------------------------
#define AQH 0
#define AQL 8192
#define AKH 16384
#define AKL 24576
#define AVH 32768
#define AVL 40960
#define APH 49152
#define APL 57344
#define ASF 65536
#define ASP 68

__global__ __launch_bounds__(256, 2)
void attn_mma() {
    extern __shared__ __align__(1024) char sma[];
    const uint32_t smb = s2u(sma);
    float* Sf  = (float*)(sma + ASF);
    float* pm  = (float*)(sma + 82944);
    float* ps  = (float*)(sma + 83968);
    float* scl = (float*)(sma + 84992);
    float* lsm = (float*)(sma + 85248);

    const int rb = (int)(gridDim.x - 1) - (int)blockIdx.x;  // heavy first
    const int bh = blockIdx.y;
    const int r0g = rb * 64;
    const int tid = threadIdx.x, wid = tid >> 5, lane = tid & 31;
    const int wm = (wid & 3) * 16, wn = (wid >> 2) * 32;
    const int r4 = lane >> 2, c2 = (lane & 3) * 2;
    const int si = tid >> 2, sq = tid & 3;        // softmax row / quarter

    const float* qb = g_q + (size_t)bh * (Tt * Dd);
    const float* kb = g_k + (size_t)bh * (Tt * Dd);
    const float* vb = g_v + (size_t)bh * (Tt * Dd);
    const int bb = bh >> 4, hh = bh & 15;
    float* ob = g_o + (size_t)bb * Tt * Cc + hh * Dd;

    // Q -> bf16 hi/lo tiles (once)
    cvt16(smb + AQH, smb + AQL, si, sq * 16,
          qb + (size_t)(r0g + si) * Dd + sq * 16);

    float oacc[4][4];
#pragma unroll
    for (int i = 0; i < 4; i++)
#pragma unroll
        for (int j = 0; j < 4; j++) oacc[i][j] = 0.f;
    float m_run = -1e30f, l_run = 0.f;

    for (int kv = 0; kv <= rb; kv++) {
        // 1. K,V -> bf16 hi/lo tiles
        cvt16(smb + AKH, smb + AKL, si, sq * 16,
              kb + (size_t)(kv * 64 + si) * Dd + sq * 16);
        cvt16(smb + AVH, smb + AVL, si, sq * 16,
              vb + (size_t)(kv * 64 + si) * Dd + sq * 16);
        __syncthreads();

        // 2. S = Q K^T (3-term bf16 split)
        float sacc[4][4];
#pragma unroll
        for (int i = 0; i < 4; i++)
#pragma unroll
            for (int j = 0; j < 4; j++) sacc[i][j] = 0.f;
        const uint32_t sa[3] = {smb + AQH, smb + AQH, smb + AQL};
        const uint32_t sb[3] = {smb + AKH, smb + AKL, smb + AKH};
#pragma unroll
        for (int term = 0; term < 3; term++) {
#pragma unroll
            for (int k16 = 0; k16 < 4; k16++) {
                const uint32_t koff = k16 * 32 + (lane >> 4) * 16;
                uint32_t a[4];
                ldsm4(a, sa[term] + SWZ((wm + (lane & 15)) * 128 + koff));
#pragma unroll
                for (int nt2 = 0; nt2 < 2; nt2++) {
                    uint32_t b4[4];
                    ldsm4(b4, sb[term] +
                               SWZ((wn + nt2 * 16 + (lane & 15)) * 128 + koff));
                    uint32_t b0[2] = {b4[0], b4[2]};
                    uint32_t b1[2] = {b4[1], b4[3]};
                    mma16816(sacc[nt2 * 2 + 0], a, b0);
                    mma16816(sacc[nt2 * 2 + 1], a, b1);
                }
            }
        }
        // store S frags (apply causal mask on diagonal tile)
        {
            const bool diag = (kv == rb);
            const int i0 = wm + r4, i1 = i0 + 8;
#pragma unroll
            for (int nt = 0; nt < 4; nt++) {
                const int c = wn + nt * 8 + c2;
                float v00 = sacc[nt][0], v01 = sacc[nt][1];
                float v10 = sacc[nt][2], v11 = sacc[nt][3];
                if (diag) {
                    if (c > i0)     v00 = -1e30f;
                    if (c + 1 > i0) v01 = -1e30f;
                    if (c > i1)     v10 = -1e30f;
                    if (c + 1 > i1) v11 = -1e30f;
                }
                *(float2*)&Sf[i0 * ASP + c] = make_float2(v00, v01);
                *(float2*)&Sf[i1 * ASP + c] = make_float2(v10, v11);
            }
        }
        __syncthreads();

        // 3. softmax: 4 threads per row, poly exp, write Ph/Pl bf16
        {
            const float* srow = Sf + si * ASP + sq * 16;
            float mx = -1e30f;
#pragma unroll
            for (int j = 0; j < 16; j++) mx = fmaxf(mx, srow[j]);
            pm[si * 4 + sq] = mx;
            __syncthreads();
            float m_tile = fmaxf(fmaxf(pm[si * 4], pm[si * 4 + 1]),
                                 fmaxf(pm[si * 4 + 2], pm[si * 4 + 3]));
            float m_new = fmaxf(m_run, m_tile);
            float sc = expapx(m_run - m_new);
            float sum = 0.f;
#pragma unroll
            for (int j = 0; j < 16; j += 2) {
                float e0 = expapx(srow[j] - m_new);
                float e1 = expapx(srow[j + 1] - m_new);
                sum += e0 + e1;
                uint32_t sw = SWZ((uint32_t)(si * 128 + (sq * 16 + j) * 2));
                st32(smb + APH + sw, pk2(e0, e1));
                st32(smb + APL + sw, pk2(e0 - bhi(e0), e1 - bhi(e1)));
            }
            ps[si * 4 + sq] = sum;
            if (sq == 0) scl[si] = sc;
            __syncthreads();
            float rs = ps[si * 4] + ps[si * 4 + 1] +
                       ps[si * 4 + 2] + ps[si * 4 + 3];
            l_run = l_run * sc + rs;
            m_run = m_new;
        }

        // 4. rescale O, then O += P V (3-term bf16 split)
        {
            float s0 = scl[wm + r4], s1 = scl[wm + r4 + 8];
#pragma unroll
            for (int nt = 0; nt < 4; nt++) {
                oacc[nt][0] *= s0; oacc[nt][1] *= s0;
                oacc[nt][2] *= s1; oacc[nt][3] *= s1;
            }
            const uint32_t pa[3] = {smb + APH, smb + APH, smb + APL};
            const uint32_t pb[3] = {smb + AVH, smb + AVL, smb + AVH};
#pragma unroll
            for (int term = 0; term < 3; term++) {
#pragma unroll
                for (int k16 = 0; k16 < 4; k16++) {
                    uint32_t a[4];
                    ldsm4(a, pa[term] + SWZ((wm + (lane & 15)) * 128 +
                                            k16 * 32 + (lane >> 4) * 16));
#pragma unroll
                    for (int nt2 = 0; nt2 < 2; nt2++) {
                        uint32_t b4[4];
                        ldsm4t(b4, pb[term] +
                                   SWZ((k16 * 16 + (lane & 15)) * 128 +
                                       (wn + nt2 * 16) * 2 + (lane >> 4) * 16));
                        uint32_t b0[2] = {b4[0], b4[1]};
                        uint32_t b1[2] = {b4[2], b4[3]};
                        mma16816(oacc[nt2 * 2 + 0], a, b0);
                        mma16816(oacc[nt2 * 2 + 1], a, b1);
                    }
                }
            }
        }
        __syncthreads();   // protect tiles before next iteration
    }

    if (sq == 0) lsm[si] = l_run;
    __syncthreads();

    {
        float i0 = 1.f / lsm[wm + r4];
        float i1 = 1.f / lsm[wm + r4 + 8];
        const int row = r0g + wm + r4;
#pragma unroll
        for (int nt = 0; nt < 4; nt++) {
            const int col = wn + nt * 8 + c2;
            *(float2*)&ob[(size_t)row * Cc + col] =
                make_float2(oacc[nt][0] * i0, oacc[nt][1] * i0);
            *(float2*)&ob[(size_t)(row + 8) * Cc + col] =
                make_float2(oacc[nt][2] * i1, oacc[nt][3] * i1);
        }
    }
}

// ---------------------------------------------------------------------------
extern "C" void kernel_launch(void* const* d_in, const int* in_sizes, int n_in,
                              void* d_out, int out_size) {
    const float* x  = (const float*)d_in[0];   // [2,2048,1024]
    const float* Wa = (const float*)d_in[1];   // [3072,1024]
    const float* Wp = (const float*)d_in[2];   // [1024,1024]
    float* y = (float*)d_out;                  // [2,2048,1024]

    static const int GSM = 65536;
    static const int ASM = 85504;
    cudaFuncSetAttribute((const void*)gemmmma<0>,
                         cudaFuncAttributeMaxDynamicSharedMemorySize, GSM);
    cudaFuncSetAttribute((const void*)gemmmma<1>,
                         cudaFuncAttributeMaxDynamicSharedMemorySize, GSM);
    cudaFuncSetAttribute((const void*)attn_mma,
                         cudaFuncAttributeMaxDynamicSharedMemorySize, ASM);

    packk<0><<<4096, 256>>>(x);
    packk<1><<<3072, 256>>>(Wa);
    packk<2><<<1024, 256>>>(Wp);

    gemmmma<0><<<dim3(24, 32), 256, GSM>>>(nullptr);   // QKV (N=3072)

    attn_mma<<<dim3(32, 32), 256, ASM>>>();

    packk<3><<<4096, 256>>>(nullptr);

    gemmmma<1><<<dim3(8, 32), 256, GSM>>>(y);          // proj (N=1024)
}

// round 11
// speedup vs baseline: 2.3839x; 1.2028x over previous
#include <cuda_runtime.h>
#include <cuda_bf16.h>
#include <math.h>
#include <stdint.h>

// Problem constants
#define Bq 2
#define Hh 16
#define Tt 2048
#define Cc 1024
#define Dd 64
#define KP 3072     // packed K (3x1024) for bf16-split GEMMs
#define NCH 48      // K chunks of 64 bf16

// Scratch (device globals: allocation-free). 16B alignment for cp.async.
__device__ __align__(16) __nv_bfloat16 g_qh[Bq*Hh*Tt*Dd];
__device__ __align__(16) __nv_bfloat16 g_ql[Bq*Hh*Tt*Dd];
__device__ __align__(16) __nv_bfloat16 g_kh[Bq*Hh*Tt*Dd];
__device__ __align__(16) __nv_bfloat16 g_kl[Bq*Hh*Tt*Dd];
__device__ __align__(16) __nv_bfloat16 g_vh[Bq*Hh*Tt*Dd];
__device__ __align__(16) __nv_bfloat16 g_vl[Bq*Hh*Tt*Dd];
__device__ __align__(16) __nv_bfloat16 g_ax[4096*KP];  // packed x      [hi|hi|lo]
__device__ __align__(16) __nv_bfloat16 g_wa[3072*KP];  // packed W_attn [hi|lo|hi]
__device__ __align__(16) __nv_bfloat16 g_wp[1024*KP];  // packed W_proj(view) [hi|lo|hi]
__device__ __align__(16) __nv_bfloat16 g_ox[4096*KP];  // packed O      [hi|hi|lo]

// ---------------------------------------------------------------------------
// Baseline-ISA helpers (sm_80+; valid on plain sm_103 target)
// ---------------------------------------------------------------------------
static __device__ __forceinline__ uint32_t s2u(const void* p) {
    uint32_t a;
    asm("{ .reg .u64 t; cvta.to.shared.u64 t, %1; cvt.u32.u64 %0, t; }"
        : "=r"(a) : "l"(p));
    return a;
}
#define SWZ(o) ((o) ^ (((o) >> 3) & 0x70))

static __device__ __forceinline__ void mma16816(float* c, const uint32_t* a,
                                                const uint32_t* b) {
    asm volatile(
        "mma.sync.aligned.m16n8k16.row.col.f32.bf16.bf16.f32 "
        "{%0,%1,%2,%3}, {%4,%5,%6,%7}, {%8,%9}, {%0,%1,%2,%3};"
        : "+f"(c[0]), "+f"(c[1]), "+f"(c[2]), "+f"(c[3])
        : "r"(a[0]), "r"(a[1]), "r"(a[2]), "r"(a[3]), "r"(b[0]), "r"(b[1]));
}
static __device__ __forceinline__ void ldsm4(uint32_t* r, uint32_t addr) {
    asm volatile("ldmatrix.sync.aligned.m8n8.x4.shared.b16 {%0,%1,%2,%3}, [%4];"
                 : "=r"(r[0]), "=r"(r[1]), "=r"(r[2]), "=r"(r[3]) : "r"(addr));
}
static __device__ __forceinline__ void ldsm4t(uint32_t* r, uint32_t addr) {
    asm volatile("ldmatrix.sync.aligned.m8n8.x4.trans.shared.b16 {%0,%1,%2,%3}, [%4];"
                 : "=r"(r[0]), "=r"(r[1]), "=r"(r[2]), "=r"(r[3]) : "r"(addr));
}
static __device__ __forceinline__ void cp16(uint32_t dst, const void* src) {
    asm volatile("cp.async.cg.shared.global [%0], [%1], 16;" :: "r"(dst), "l"(src));
}
#define CP_COMMIT() asm volatile("cp.async.commit_group;" ::: "memory")
#define CP_WAIT1()  asm volatile("cp.async.wait_group 1;" ::: "memory")

static __device__ __forceinline__ uint32_t pk2(float a, float b) {
    __nv_bfloat162 t = __floats2bfloat162_rn(a, b);
    return *reinterpret_cast<uint32_t*>(&t);
}
static __device__ __forceinline__ float bhi(float x) {
    return __bfloat162float(__float2bfloat16(x));
}

// e^x for x <= 0 via FMA-pipe poly (no MUFU). err ~2.4e-6 rel.
static __device__ __forceinline__ float expapx(float x) {
    float y = fmaxf(x, -87.0f) * 1.44269504f;
    float z = y + 12582912.0f;          // round-to-nearest int (magic)
    float r = z - 12582912.0f;
    float f = y - r;                    // f in [-0.5, 0.5]
    float p = 1.33335581e-3f;
    p = fmaf(p, f, 9.61812911e-3f);
    p = fmaf(p, f, 5.55041087e-2f);
    p = fmaf(p, f, 2.40226507e-1f);
    p = fmaf(p, f, 6.93147181e-1f);
    p = fmaf(p, f, 1.0f);
    return p * __int_as_float((__float_as_int(z) << 23) + 0x3F800000);
}

// ---------------------------------------------------------------------------
// Pack kernels (inputs only)
// ---------------------------------------------------------------------------
template<int KIND>
__global__ __launch_bounds__(256)
void packk(const float* __restrict__ src) {
    const int m = blockIdx.x;
    const int c4 = threadIdx.x * 4;
    const float* sp;
    __nv_bfloat16* dst;
    if (KIND == 0)      { sp = src + (size_t)m * 1024 + c4; dst = g_ax; }
    else if (KIND == 1) { sp = src + (size_t)m * 1024 + c4; dst = g_wa; }
    else                { sp = src + (((c4 >> 6) << 16) + (m << 6) + (c4 & 63)); dst = g_wp; }

    float4 v = *(const float4*)sp;
    float vv[4] = {v.x, v.y, v.z, v.w};
    union U { __nv_bfloat16 b[4]; uint2 u; };
    U H, L;
#pragma unroll
    for (int j = 0; j < 4; j++) {
        H.b[j] = __float2bfloat16(vv[j]);
        L.b[j] = __float2bfloat16(vv[j] - __bfloat162float(H.b[j]));
    }
    __nv_bfloat16* row = dst + (size_t)m * KP;
    *(uint2*)(row + c4) = H.u;
    if (KIND == 0) {
        *(uint2*)(row + 1024 + c4) = H.u;
        *(uint2*)(row + 2048 + c4) = L.u;
    } else {
        *(uint2*)(row + 1024 + c4) = L.u;
        *(uint2*)(row + 2048 + c4) = H.u;
    }
}

// ---------------------------------------------------------------------------
// bf16 mma.sync GEMM. MODE 0: epilogue writes q/k/v hi/lo bf16 tensors.
// MODE 1: A=g_ox, W=g_wp, writes fp32 out.
// ---------------------------------------------------------------------------
template<int MODE>
__global__ __launch_bounds__(256, 2)
void gemmmma(float* __restrict__ out) {
    extern __shared__ __align__(1024) char sm[];
    const uint32_t smb = s2u(sm);
    const int tid = threadIdx.x, wid = tid >> 5, lane = tid & 31;
    const int bm = blockIdx.y * 128, bn = blockIdx.x * 128;
    const int wm = (wid & 3) * 32, wn = (wid >> 2) * 64;

    const __nv_bfloat16* __restrict__ A = MODE ? g_ox : g_ax;
    const __nv_bfloat16* __restrict__ W = MODE ? g_wp : g_wa;

    auto load = [&](int c, int s) {
        const __nv_bfloat16* Ab = A + (size_t)bm * KP + c * 64;
        const __nv_bfloat16* Wb = W + (size_t)bn * KP + c * 64;
        uint32_t as = smb + s * 16384;
        uint32_t bs = smb + 32768 + s * 16384;
#pragma unroll
        for (int t = 0; t < 4; t++) {
            int idx = tid + t * 256;
            int row = idx >> 3, col = idx & 7;
            uint32_t so = SWZ(row * 128 + col * 16);
            cp16(as + so, Ab + (size_t)row * KP + col * 8);
            cp16(bs + so, Wb + (size_t)row * KP + col * 8);
        }
    };

    float acc[2][8][4];
#pragma unroll
    for (int i = 0; i < 2; i++)
#pragma unroll
        for (int j = 0; j < 8; j++)
#pragma unroll
            for (int q = 0; q < 4; q++) acc[i][j][q] = 0.f;

    load(0, 0); CP_COMMIT();
    load(1, 1); CP_COMMIT();

    for (int c = 0; c < NCH; c++) {
        CP_WAIT1();
        __syncthreads();
        const uint32_t ab = smb + (c & 1) * 16384;
        const uint32_t bb = smb + 32768 + (c & 1) * 16384;
#pragma unroll
        for (int k16 = 0; k16 < 4; k16++) {
            const int colb = k16 * 32 + (lane >> 4) * 16;
            uint32_t a[2][4], b4[4][4];
#pragma unroll
            for (int mt = 0; mt < 2; mt++) {
                int row = wm + mt * 16 + (lane & 15);
                ldsm4(a[mt], ab + SWZ(row * 128 + colb));
            }
#pragma unroll
            for (int nt2 = 0; nt2 < 4; nt2++) {
                int row = wn + nt2 * 16 + (lane & 15);
                ldsm4(b4[nt2], bb + SWZ(row * 128 + colb));
            }
#pragma unroll
            for (int mt = 0; mt < 2; mt++)
#pragma unroll
                for (int nt2 = 0; nt2 < 4; nt2++) {
                    uint32_t b0[2] = {b4[nt2][0], b4[nt2][2]};
                    uint32_t b1[2] = {b4[nt2][1], b4[nt2][3]};
                    mma16816(acc[mt][nt2 * 2 + 0], a[mt], b0);
                    mma16816(acc[mt][nt2 * 2 + 1], a[mt], b1);
                }
        }
        __syncthreads();
        if (c + 2 < NCH) load(c + 2, c & 1);
        CP_COMMIT();
    }

    const int r4 = lane >> 2, c2 = (lane & 3) * 2;
#pragma unroll
    for (int mt = 0; mt < 2; mt++) {
#pragma unroll
        for (int nt = 0; nt < 8; nt++) {
            const int m0 = bm + wm + mt * 16 + r4;
            const int n  = bn + wn + nt * 8 + c2;
            float2 v0 = make_float2(acc[mt][nt][0], acc[mt][nt][1]);
            float2 v1 = make_float2(acc[mt][nt][2], acc[mt][nt][3]);
            if (MODE == 0) {
                const int which = n >> 10, cc = n & 1023;
                const int h = cc >> 6, d = cc & 63;
                const int b = m0 >> 11, t0 = m0 & 2047;
                __nv_bfloat16 *dh, *dl;
                if (which == 0)      { dh = g_qh; dl = g_ql; }
                else if (which == 1) { dh = g_kh; dl = g_kl; }
                else                 { dh = g_vh; dl = g_vl; }
                const size_t base = ((size_t)(b * Hh + h) * Tt + t0) * Dd + d;
                *(uint32_t*)&dh[base] = pk2(v0.x, v0.y);
                *(uint32_t*)&dl[base] = pk2(v0.x - bhi(v0.x), v0.y - bhi(v0.y));
                *(uint32_t*)&dh[base + 8 * Dd] = pk2(v1.x, v1.y);
                *(uint32_t*)&dl[base + 8 * Dd] =
                    pk2(v1.x - bhi(v1.x), v1.y - bhi(v1.y));
            } else {
                *(float2*)&out[(size_t)m0 * Cc + n] = v0;
                *(float2*)&out[(size_t)(m0 + 8) * Cc + n] = v1;
            }
        }
    }
}

// ---------------------------------------------------------------------------
// FA2-style tensor-core causal attention, bf16 hi/lo 3-term.
// CTA = 128 q-rows of one (b,h); 8 warps x 16 rows, warp spans all 64 kv cols.
// S and P live in registers; softmax via quad shuffles. K/V tiles cp.async
// double-buffered (pre-split bf16 from the QKV epilogue). O -> g_ox direct.
// Smem: Qh 0..16K, Ql 16K..32K, KV buf s at 32768+s*32768
//       {Kh +0, Kl +8192, Vh +16384, Vl +24576}. Total 98304.
// ---------------------------------------------------------------------------
__global__ __launch_bounds__(256, 2)
void attn_mma() {
    extern __shared__ __align__(1024) char sma[];
    const uint32_t smb = s2u(sma);
    const int rb = 15 - (int)blockIdx.x;    // heavy row-blocks first
    const int bh = blockIdx.y;
    const int r0g = rb * 128;
    const int tid = threadIdx.x, wid = tid >> 5, lane = tid & 31;
    const int wm = wid * 16;
    const int r4 = lane >> 2, c2 = (lane & 3) * 2;
    const int row0 = r0g + wm + r4, row1 = row0 + 8;
    const int bb = bh >> 4, hh = bh & 15;
    const size_t hbase = (size_t)bh * (Tt * Dd);

    // Q tiles (hi/lo) -> smem once
    {
        const __nv_bfloat16* qs[2] = {g_qh, g_ql};
#pragma unroll
        for (int t = 0; t < 8; t++) {
            int comp = t >> 2;
            int q = ((t & 3) << 8) + tid;
            int row = q >> 3, cl = q & 7;
            cp16(smb + comp * 16384 + SWZ(row * 128 + cl * 16),
                 qs[comp] + hbase + (size_t)(r0g + row) * Dd + cl * 8);
        }
        CP_COMMIT();
    }

    const int ntiles = 2 * rb + 2;
    auto loadkv = [&](int c, int s) {
        const __nv_bfloat16* gp[4] = {g_kh, g_kl, g_vh, g_vl};
        uint32_t bsm = smb + 32768 + s * 32768;
        size_t src0 = hbase + (size_t)c * 64 * Dd;
#pragma unroll
        for (int t = 0; t < 8; t++) {
            int comp = t >> 1;
            int q = ((t & 1) << 8) + tid;
            int row = q >> 3, cl = q & 7;
            cp16(bsm + comp * 8192 + SWZ(row * 128 + cl * 16),
                 gp[comp] + src0 + row * Dd + cl * 8);
        }
    };
    loadkv(0, 0); CP_COMMIT();
    loadkv(1, 1); CP_COMMIT();

    float oacc[8][4];
#pragma unroll
    for (int i = 0; i < 8; i++)
#pragma unroll
        for (int j = 0; j < 4; j++) oacc[i][j] = 0.f;
    float m0 = -1e30f, m1 = -1e30f, l0 = 0.f, l1 = 0.f;

    for (int c = 0; c < ntiles; c++) {
        CP_WAIT1();
        __syncthreads();
        const uint32_t kh = smb + 32768 + (c & 1) * 32768;
        const uint32_t kl = kh + 8192, vh = kh + 16384, vl = kh + 24576;

        // ---- S = Q K^T (3-term) ----
        float sacc[8][4];
#pragma unroll
        for (int i = 0; i < 8; i++)
#pragma unroll
            for (int j = 0; j < 4; j++) sacc[i][j] = 0.f;
#pragma unroll
        for (int k16 = 0; k16 < 4; k16++) {
            const int colb = k16 * 32 + (lane >> 4) * 16;
            uint32_t ah[4], al[4];
            ldsm4(ah, smb + SWZ((wm + (lane & 15)) * 128 + colb));
            ldsm4(al, smb + 16384 + SWZ((wm + (lane & 15)) * 128 + colb));
#pragma unroll
            for (int nt4 = 0; nt4 < 4; nt4++) {
                uint32_t kh4[4], kl4[4];
                uint32_t ra = SWZ((nt4 * 16 + (lane & 15)) * 128 + colb);
                ldsm4(kh4, kh + ra);
                ldsm4(kl4, kl + ra);
                uint32_t bh0[2] = {kh4[0], kh4[2]}, bh1[2] = {kh4[1], kh4[3]};
                uint32_t bl0[2] = {kl4[0], kl4[2]}, bl1[2] = {kl4[1], kl4[3]};
                mma16816(sacc[nt4 * 2 + 0], ah, bh0);
                mma16816(sacc[nt4 * 2 + 1], ah, bh1);
                mma16816(sacc[nt4 * 2 + 0], ah, bl0);
                mma16816(sacc[nt4 * 2 + 1], ah, bl1);
                mma16816(sacc[nt4 * 2 + 0], al, bh0);
                mma16816(sacc[nt4 * 2 + 1], al, bh1);
            }
        }

        // ---- causal mask (diagonal tiles only) ----
        if (c >= 2 * rb) {
#pragma unroll
            for (int nt = 0; nt < 8; nt++) {
                const int cg = c * 64 + nt * 8 + c2;
                if (cg > row0)     sacc[nt][0] = -1e30f;
                if (cg + 1 > row0) sacc[nt][1] = -1e30f;
                if (cg > row1)     sacc[nt][2] = -1e30f;
                if (cg + 1 > row1) sacc[nt][3] = -1e30f;
            }
        }

        // ---- register softmax (quad shuffles) ----
        {
            float mx0 = -1e30f, mx1 = -1e30f;
#pragma unroll
            for (int nt = 0; nt < 8; nt++) {
                mx0 = fmaxf(mx0, fmaxf(sacc[nt][0], sacc[nt][1]));
                mx1 = fmaxf(mx1, fmaxf(sacc[nt][2], sacc[nt][3]));
            }
            mx0 = fmaxf(mx0, __shfl_xor_sync(0xffffffffu, mx0, 1));
            mx0 = fmaxf(mx0, __shfl_xor_sync(0xffffffffu, mx0, 2));
            mx1 = fmaxf(mx1, __shfl_xor_sync(0xffffffffu, mx1, 1));
            mx1 = fmaxf(mx1, __shfl_xor_sync(0xffffffffu, mx1, 2));
            float mn0 = fmaxf(m0, mx0), mn1 = fmaxf(m1, mx1);
            float sc0 = expapx(m0 - mn0), sc1 = expapx(m1 - mn1);
            float s0 = 0.f, s1 = 0.f;
#pragma unroll
            for (int nt = 0; nt < 8; nt++) {
                float e0 = expapx(sacc[nt][0] - mn0);
                float e1 = expapx(sacc[nt][1] - mn0);
                float e2 = expapx(sacc[nt][2] - mn1);
                float e3 = expapx(sacc[nt][3] - mn1);
                sacc[nt][0] = e0; sacc[nt][1] = e1;
                sacc[nt][2] = e2; sacc[nt][3] = e3;
                s0 += e0 + e1; s1 += e2 + e3;
                oacc[nt][0] *= sc0; oacc[nt][1] *= sc0;
                oacc[nt][2] *= sc1; oacc[nt][3] *= sc1;
            }
            s0 += __shfl_xor_sync(0xffffffffu, s0, 1);
            s0 += __shfl_xor_sync(0xffffffffu, s0, 2);
            s1 += __shfl_xor_sync(0xffffffffu, s1, 1);
            s1 += __shfl_xor_sync(0xffffffffu, s1, 2);
            l0 = l0 * sc0 + s0; l1 = l1 * sc1 + s1;
            m0 = mn0; m1 = mn1;
        }

        // ---- O += P V (3-term; P frags built from sacc registers) ----
#pragma unroll
        for (int kt = 0; kt < 4; kt++) {
            float e00 = sacc[2*kt][0],   e01 = sacc[2*kt][1];
            float e02 = sacc[2*kt][2],   e03 = sacc[2*kt][3];
            float e10 = sacc[2*kt+1][0], e11 = sacc[2*kt+1][1];
            float e12 = sacc[2*kt+1][2], e13 = sacc[2*kt+1][3];
            uint32_t ph[4] = {pk2(e00, e01), pk2(e02, e03),
                              pk2(e10, e11), pk2(e12, e13)};
            uint32_t pl[4] = {pk2(e00 - bhi(e00), e01 - bhi(e01)),
                              pk2(e02 - bhi(e02), e03 - bhi(e03)),
                              pk2(e10 - bhi(e10), e11 - bhi(e11)),
                              pk2(e12 - bhi(e12), e13 - bhi(e13))};
#pragma unroll
            for (int nt2 = 0; nt2 < 4; nt2++) {
                uint32_t ra = SWZ((kt * 16 + (lane & 15)) * 128 +
                                  nt2 * 32 + (lane >> 4) * 16);
                uint32_t v4h[4], v4l[4];
                ldsm4t(v4h, vh + ra);
                ldsm4t(v4l, vl + ra);
                uint32_t bh0[2] = {v4h[0], v4h[1]}, bh1[2] = {v4h[2], v4h[3]};
                uint32_t bl0[2] = {v4l[0], v4l[1]}, bl1[2] = {v4l[2], v4l[3]};
                mma16816(oacc[nt2 * 2 + 0], ph, bh0);
                mma16816(oacc[nt2 * 2 + 1], ph, bh1);
                mma16816(oacc[nt2 * 2 + 0], ph, bl0);
                mma16816(oacc[nt2 * 2 + 1], ph, bl1);
                mma16816(oacc[nt2 * 2 + 0], pl, bh0);
                mma16816(oacc[nt2 * 2 + 1], pl, bh1);
            }
        }
        __syncthreads();
        if (c + 2 < ntiles) loadkv(c + 2, c & 1);
        CP_COMMIT();
    }

    // ---- finalize: O/l -> g_ox packed [hi|hi|lo] ----
    {
        float inv0 = 1.f / l0, inv1 = 1.f / l1;
        const size_t mg0 = (size_t)bb * Tt + row0;
#pragma unroll
        for (int nt = 0; nt < 8; nt++) {
            const int col = hh * 64 + nt * 8 + c2;
            float f0 = oacc[nt][0] * inv0, f1 = oacc[nt][1] * inv0;
            float f2 = oacc[nt][2] * inv1, f3 = oacc[nt][3] * inv1;
            size_t b0 = mg0 * KP + col;
            uint32_t h0 = pk2(f0, f1);
            *(uint32_t*)&g_ox[b0] = h0;
            *(uint32_t*)&g_ox[b0 + 1024] = h0;
            *(uint32_t*)&g_ox[b0 + 2048] = pk2(f0 - bhi(f0), f1 - bhi(f1));
            size_t b1 = (mg0 + 8) * KP + col;
            uint32_t h1 = pk2(f2, f3);
            *(uint32_t*)&g_ox[b1] = h1;
            *(uint32_t*)&g_ox[b1 + 1024] = h1;
            *(uint32_t*)&g_ox[b1 + 2048] = pk2(f2 - bhi(f2), f3 - bhi(f3));
        }
    }
}

// ---------------------------------------------------------------------------
extern "C" void kernel_launch(void* const* d_in, const int* in_sizes, int n_in,
                              void* d_out, int out_size) {
    const float* x  = (const float*)d_in[0];   // [2,2048,1024]
    const float* Wa = (const float*)d_in[1];   // [3072,1024]
    const float* Wp = (const float*)d_in[2];   // [1024,1024]
    float* y = (float*)d_out;                  // [2,2048,1024]

    static const int GSM = 65536;
    static const int ASM = 98304;
    cudaFuncSetAttribute((const void*)gemmmma<0>,
                         cudaFuncAttributeMaxDynamicSharedMemorySize, GSM);
    cudaFuncSetAttribute((const void*)gemmmma<1>,
                         cudaFuncAttributeMaxDynamicSharedMemorySize, GSM);
    cudaFuncSetAttribute((const void*)attn_mma,
                         cudaFuncAttributeMaxDynamicSharedMemorySize, ASM);

    packk<0><<<4096, 256>>>(x);
    packk<1><<<3072, 256>>>(Wa);
    packk<2><<<1024, 256>>>(Wp);

    gemmmma<0><<<dim3(24, 32), 256, GSM>>>(nullptr);   // QKV (N=3072)

    attn_mma<<<dim3(16, 32), 256, ASM>>>();

    gemmmma<1><<<dim3(8, 32), 256, GSM>>>(y);          // proj (N=1024)
}

// round 13
// speedup vs baseline: 3.0627x; 1.2847x over previous
#include <cuda_runtime.h>
#include <cuda_bf16.h>
#include <cuda_fp16.h>
#include <math.h>
#include <stdint.h>

// Problem constants
#define Bq 2
#define Hh 16
#define Tt 2048
#define Cc 1024
#define Dd 64
#define KP 3072     // packed K (3x1024) for the bf16-split QKV GEMM
#define NCH 48      // K chunks of 64 bf16 (QKV)
#define NCHP 16     // K chunks of 64 fp16 (proj, K=1024)

// Scratch (device globals: allocation-free). 16B alignment for cp.async.
__device__ __align__(16) __nv_bfloat16 g_qh[Bq*Hh*Tt*Dd];
__device__ __align__(16) __nv_bfloat16 g_ql[Bq*Hh*Tt*Dd];
__device__ __align__(16) __nv_bfloat16 g_kh[Bq*Hh*Tt*Dd];
__device__ __align__(16) __nv_bfloat16 g_kl[Bq*Hh*Tt*Dd];
__device__ __align__(16) __half       g_vf[Bq*Hh*Tt*Dd];   // V fp16 single
__device__ __align__(16) __nv_bfloat16 g_ax[4096*KP];  // packed x      [hi|hi|lo]
__device__ __align__(16) __nv_bfloat16 g_wa[3072*KP];  // packed W_attn [hi|lo|hi]
__device__ __align__(16) __half       g_wpf[1024*1024]; // W_proj(view) fp16 single
__device__ __align__(16) __half       g_ox[4096*1024];  // O fp16 single

// ---------------------------------------------------------------------------
// Baseline-ISA helpers (sm_80+; valid on plain sm_103 target)
// ---------------------------------------------------------------------------
static __device__ __forceinline__ uint32_t s2u(const void* p) {
    uint32_t a;
    asm("{ .reg .u64 t; cvta.to.shared.u64 t, %1; cvt.u32.u64 %0, t; }"
        : "=r"(a) : "l"(p));
    return a;
}
#define SWZ(o) ((o) ^ (((o) >> 3) & 0x70))

static __device__ __forceinline__ void mma16816(float* c, const uint32_t* a,
                                                const uint32_t* b) {
    asm volatile(
        "mma.sync.aligned.m16n8k16.row.col.f32.bf16.bf16.f32 "
        "{%0,%1,%2,%3}, {%4,%5,%6,%7}, {%8,%9}, {%0,%1,%2,%3};"
        : "+f"(c[0]), "+f"(c[1]), "+f"(c[2]), "+f"(c[3])
        : "r"(a[0]), "r"(a[1]), "r"(a[2]), "r"(a[3]), "r"(b[0]), "r"(b[1]));
}
static __device__ __forceinline__ void mmah(float* c, const uint32_t* a,
                                            const uint32_t* b) {
    asm volatile(
        "mma.sync.aligned.m16n8k16.row.col.f32.f16.f16.f32 "
        "{%0,%1,%2,%3}, {%4,%5,%6,%7}, {%8,%9}, {%0,%1,%2,%3};"
        : "+f"(c[0]), "+f"(c[1]), "+f"(c[2]), "+f"(c[3])
        : "r"(a[0]), "r"(a[1]), "r"(a[2]), "r"(a[3]), "r"(b[0]), "r"(b[1]));
}
static __device__ __forceinline__ void ldsm4(uint32_t* r, uint32_t addr) {
    asm volatile("ldmatrix.sync.aligned.m8n8.x4.shared.b16 {%0,%1,%2,%3}, [%4];"
                 : "=r"(r[0]), "=r"(r[1]), "=r"(r[2]), "=r"(r[3]) : "r"(addr));
}
static __device__ __forceinline__ void ldsm4t(uint32_t* r, uint32_t addr) {
    asm volatile("ldmatrix.sync.aligned.m8n8.x4.trans.shared.b16 {%0,%1,%2,%3}, [%4];"
                 : "=r"(r[0]), "=r"(r[1]), "=r"(r[2]), "=r"(r[3]) : "r"(addr));
}
static __device__ __forceinline__ void cp16(uint32_t dst, const void* src) {
    asm volatile("cp.async.cg.shared.global [%0], [%1], 16;" :: "r"(dst), "l"(src));
}
#define CP_COMMIT() asm volatile("cp.async.commit_group;" ::: "memory")
#define CP_WAIT1()  asm volatile("cp.async.wait_group 1;" ::: "memory")

static __device__ __forceinline__ uint32_t pk2(float a, float b) {
    __nv_bfloat162 t = __floats2bfloat162_rn(a, b);
    return *reinterpret_cast<uint32_t*>(&t);
}
static __device__ __forceinline__ uint32_t pkh2(float a, float b) {
    __half2 t = __floats2half2_rn(a, b);
    return *reinterpret_cast<uint32_t*>(&t);
}
static __device__ __forceinline__ float bhi(float x) {
    return __bfloat162float(__float2bfloat16(x));
}

// e^x for x <= 0 via FMA-pipe poly (no MUFU). err ~2.4e-6 rel.
static __device__ __forceinline__ float expapx(float x) {
    float y = fmaxf(x, -87.0f) * 1.44269504f;
    float z = y + 12582912.0f;          // round-to-nearest int (magic)
    float r = z - 12582912.0f;
    float f = y - r;                    // f in [-0.5, 0.5]
    float p = 1.33335581e-3f;
    p = fmaf(p, f, 9.61812911e-3f);
    p = fmaf(p, f, 5.55041087e-2f);
    p = fmaf(p, f, 2.40226507e-1f);
    p = fmaf(p, f, 6.93147181e-1f);
    p = fmaf(p, f, 1.0f);
    return p * __int_as_float((__float_as_int(z) << 23) + 0x3F800000);
}

// ---------------------------------------------------------------------------
// Pack kernels.
// KIND 0: x -> g_ax [hi|hi|lo]   KIND 1: W_attn -> g_wa [hi|lo|hi]
// KIND 2: W_proj(view) -> g_wpf fp16 single
// ---------------------------------------------------------------------------
template<int KIND>
__global__ __launch_bounds__(256)
void packk(const float* __restrict__ src) {
    const int m = blockIdx.x;
    const int c4 = threadIdx.x * 4;
    if (KIND == 2) {
        const float* sp = src + (((c4 >> 6) << 16) + (m << 6) + (c4 & 63));
        float4 v = *(const float4*)sp;
        uint2 u = make_uint2(pkh2(v.x, v.y), pkh2(v.z, v.w));
        *(uint2*)&g_wpf[(size_t)m * 1024 + c4] = u;
        return;
    }
    const float* sp = src + (size_t)m * 1024 + c4;
    __nv_bfloat16* dst = (KIND == 0) ? g_ax : g_wa;

    float4 v = *(const float4*)sp;
    float vv[4] = {v.x, v.y, v.z, v.w};
    union U { __nv_bfloat16 b[4]; uint2 u; };
    U H, L;
#pragma unroll
    for (int j = 0; j < 4; j++) {
        H.b[j] = __float2bfloat16(vv[j]);
        L.b[j] = __float2bfloat16(vv[j] - __bfloat162float(H.b[j]));
    }
    __nv_bfloat16* row = dst + (size_t)m * KP;
    *(uint2*)(row + c4) = H.u;
    if (KIND == 0) {
        *(uint2*)(row + 1024 + c4) = H.u;
        *(uint2*)(row + 2048 + c4) = L.u;
    } else {
        *(uint2*)(row + 1024 + c4) = L.u;
        *(uint2*)(row + 2048 + c4) = H.u;
    }
}

// ---------------------------------------------------------------------------
// QKV GEMM: bf16 3-term, K'=3072. Epilogue writes q/k hi/lo bf16, v fp16.
// ---------------------------------------------------------------------------
__global__ __launch_bounds__(256, 2)
void gemmqkv() {
    extern __shared__ __align__(1024) char sm[];
    const uint32_t smb = s2u(sm);
    const int tid = threadIdx.x, wid = tid >> 5, lane = tid & 31;
    const int bm = blockIdx.y * 128, bn = blockIdx.x * 128;
    const int wm = (wid & 3) * 32, wn = (wid >> 2) * 64;

    auto load = [&](int c, int s) {
        const __nv_bfloat16* Ab = g_ax + (size_t)bm * KP + c * 64;
        const __nv_bfloat16* Wb = g_wa + (size_t)bn * KP + c * 64;
        uint32_t as = smb + s * 16384;
        uint32_t bs = smb + 32768 + s * 16384;
#pragma unroll
        for (int t = 0; t < 4; t++) {
            int idx = tid + t * 256;
            int row = idx >> 3, col = idx & 7;
            uint32_t so = SWZ(row * 128 + col * 16);
            cp16(as + so, Ab + (size_t)row * KP + col * 8);
            cp16(bs + so, Wb + (size_t)row * KP + col * 8);
        }
    };

    float acc[2][8][4];
#pragma unroll
    for (int i = 0; i < 2; i++)
#pragma unroll
        for (int j = 0; j < 8; j++)
#pragma unroll
            for (int q = 0; q < 4; q++) acc[i][j][q] = 0.f;

    load(0, 0); CP_COMMIT();
    load(1, 1); CP_COMMIT();

    for (int c = 0; c < NCH; c++) {
        CP_WAIT1();
        __syncthreads();
        const uint32_t ab = smb + (c & 1) * 16384;
        const uint32_t bb = smb + 32768 + (c & 1) * 16384;
#pragma unroll
        for (int k16 = 0; k16 < 4; k16++) {
            const int colb = k16 * 32 + (lane >> 4) * 16;
            uint32_t a[2][4], b4[4][4];
#pragma unroll
            for (int mt = 0; mt < 2; mt++) {
                int row = wm + mt * 16 + (lane & 15);
                ldsm4(a[mt], ab + SWZ(row * 128 + colb));
            }
#pragma unroll
            for (int nt2 = 0; nt2 < 4; nt2++) {
                int row = wn + nt2 * 16 + (lane & 15);
                ldsm4(b4[nt2], bb + SWZ(row * 128 + colb));
            }
#pragma unroll
            for (int mt = 0; mt < 2; mt++)
#pragma unroll
                for (int nt2 = 0; nt2 < 4; nt2++) {
                    uint32_t b0[2] = {b4[nt2][0], b4[nt2][2]};
                    uint32_t b1[2] = {b4[nt2][1], b4[nt2][3]};
                    mma16816(acc[mt][nt2 * 2 + 0], a[mt], b0);
                    mma16816(acc[mt][nt2 * 2 + 1], a[mt], b1);
                }
        }
        __syncthreads();
        if (c + 2 < NCH) load(c + 2, c & 1);
        CP_COMMIT();
    }

    const int r4 = lane >> 2, c2 = (lane & 3) * 2;
#pragma unroll
    for (int mt = 0; mt < 2; mt++) {
#pragma unroll
        for (int nt = 0; nt < 8; nt++) {
            const int m0 = bm + wm + mt * 16 + r4;
            const int n  = bn + wn + nt * 8 + c2;
            float2 v0 = make_float2(acc[mt][nt][0], acc[mt][nt][1]);
            float2 v1 = make_float2(acc[mt][nt][2], acc[mt][nt][3]);
            const int which = n >> 10, cc = n & 1023;
            const int h = cc >> 6, d = cc & 63;
            const int b = m0 >> 11, t0 = m0 & 2047;
            const size_t base = ((size_t)(b * Hh + h) * Tt + t0) * Dd + d;
            if (which == 2) {
                *(uint32_t*)&g_vf[base] = pkh2(v0.x, v0.y);
                *(uint32_t*)&g_vf[base + 8 * Dd] = pkh2(v1.x, v1.y);
            } else {
                __nv_bfloat16* dh = which ? g_kh : g_qh;
                __nv_bfloat16* dl = which ? g_kl : g_ql;
                *(uint32_t*)&dh[base] = pk2(v0.x, v0.y);
                *(uint32_t*)&dl[base] = pk2(v0.x - bhi(v0.x), v0.y - bhi(v0.y));
                *(uint32_t*)&dh[base + 8 * Dd] = pk2(v1.x, v1.y);
                *(uint32_t*)&dl[base + 8 * Dd] =
                    pk2(v1.x - bhi(v1.x), v1.y - bhi(v1.y));
            }
        }
    }
}

// ---------------------------------------------------------------------------
// Projection GEMM: fp16 single-term, K=1024. A=g_ox, W=g_wpf, out fp32.
// ---------------------------------------------------------------------------
__global__ __launch_bounds__(256, 2)
void gemmproj(float* __restrict__ out) {
    extern __shared__ __align__(1024) char sm[];
    const uint32_t smb = s2u(sm);
    const int tid = threadIdx.x, wid = tid >> 5, lane = tid & 31;
    const int bm = blockIdx.y * 128, bn = blockIdx.x * 128;
    const int wm = (wid & 3) * 32, wn = (wid >> 2) * 64;

    auto load = [&](int c, int s) {
        const __half* Ab = g_ox + (size_t)bm * 1024 + c * 64;
        const __half* Wb = g_wpf + (size_t)bn * 1024 + c * 64;
        uint32_t as = smb + s * 16384;
        uint32_t bs = smb + 32768 + s * 16384;
#pragma unroll
        for (int t = 0; t < 4; t++) {
            int idx = tid + t * 256;
            int row = idx >> 3, col = idx & 7;
            uint32_t so = SWZ(row * 128 + col * 16);
            cp16(as + so, Ab + (size_t)row * 1024 + col * 8);
            cp16(bs + so, Wb + (size_t)row * 1024 + col * 8);
        }
    };

    float acc[2][8][4];
#pragma unroll
    for (int i = 0; i < 2; i++)
#pragma unroll
        for (int j = 0; j < 8; j++)
#pragma unroll
            for (int q = 0; q < 4; q++) acc[i][j][q] = 0.f;

    load(0, 0); CP_COMMIT();
    load(1, 1); CP_COMMIT();

    for (int c = 0; c < NCHP; c++) {
        CP_WAIT1();
        __syncthreads();
        const uint32_t ab = smb + (c & 1) * 16384;
        const uint32_t bb = smb + 32768 + (c & 1) * 16384;
#pragma unroll
        for (int k16 = 0; k16 < 4; k16++) {
            const int colb = k16 * 32 + (lane >> 4) * 16;
            uint32_t a[2][4], b4[4][4];
#pragma unroll
            for (int mt = 0; mt < 2; mt++) {
                int row = wm + mt * 16 + (lane & 15);
                ldsm4(a[mt], ab + SWZ(row * 128 + colb));
            }
#pragma unroll
            for (int nt2 = 0; nt2 < 4; nt2++) {
                int row = wn + nt2 * 16 + (lane & 15);
                ldsm4(b4[nt2], bb + SWZ(row * 128 + colb));
            }
#pragma unroll
            for (int mt = 0; mt < 2; mt++)
#pragma unroll
                for (int nt2 = 0; nt2 < 4; nt2++) {
                    uint32_t b0[2] = {b4[nt2][0], b4[nt2][2]};
                    uint32_t b1[2] = {b4[nt2][1], b4[nt2][3]};
                    mmah(acc[mt][nt2 * 2 + 0], a[mt], b0);
                    mmah(acc[mt][nt2 * 2 + 1], a[mt], b1);
                }
        }
        __syncthreads();
        if (c + 2 < NCHP) load(c + 2, c & 1);
        CP_COMMIT();
    }

    const int r4 = lane >> 2, c2 = (lane & 3) * 2;
#pragma unroll
    for (int mt = 0; mt < 2; mt++) {
#pragma unroll
        for (int nt = 0; nt < 8; nt++) {
            const int m0 = bm + wm + mt * 16 + r4;
            const int n  = bn + wn + nt * 8 + c2;
            *(float2*)&out[(size_t)m0 * Cc + n] =
                make_float2(acc[mt][nt][0], acc[mt][nt][1]);
            *(float2*)&out[(size_t)(m0 + 8) * Cc + n] =
                make_float2(acc[mt][nt][2], acc[mt][nt][3]);
        }
    }
}

// ---------------------------------------------------------------------------
// FA2-style attention: QK^T bf16 3-term, PV fp16 single-term.
// CTA = 128 q-rows; 8 warps x 16 rows, warp spans all 64 kv cols.
// Smem: Qh 0, Ql 16384; KV stage s at 32768+s*24576 {Kh +0, Kl +8192, Vf +16384}
// Total 81920.
// ---------------------------------------------------------------------------
__global__ __launch_bounds__(256, 2)
void attn_mma() {
    extern __shared__ __align__(1024) char sma[];
    const uint32_t smb = s2u(sma);
    const int rb = 15 - (int)blockIdx.x;    // heavy row-blocks first
    const int bh = blockIdx.y;
    const int r0g = rb * 128;
    const int tid = threadIdx.x, wid = tid >> 5, lane = tid & 31;
    const int wm = wid * 16;
    const int r4 = lane >> 2, c2 = (lane & 3) * 2;
    const int row0 = r0g + wm + r4, row1 = row0 + 8;
    const int bb = bh >> 4, hh = bh & 15;
    const size_t hbase = (size_t)bh * (Tt * Dd);

    // Q tiles (hi/lo) -> smem once
    {
        const __nv_bfloat16* qs[2] = {g_qh, g_ql};
#pragma unroll
        for (int t = 0; t < 8; t++) {
            int comp = t >> 2;
            int q = ((t & 3) << 8) + tid;
            int row = q >> 3, cl = q & 7;
            cp16(smb + comp * 16384 + SWZ(row * 128 + cl * 16),
                 qs[comp] + hbase + (size_t)(r0g + row) * Dd + cl * 8);
        }
        CP_COMMIT();
    }

    const int ntiles = 2 * rb + 2;
    auto loadkv = [&](int c, int s) {
        uint32_t bsm = smb + 32768 + s * 24576;
        size_t src0 = hbase + (size_t)c * 64 * Dd;
#pragma unroll
        for (int t = 0; t < 6; t++) {
            int comp = t >> 1;
            int q = ((t & 1) << 8) + tid;
            int row = q >> 3, cl = q & 7;
            const void* src = (comp == 0) ? (const void*)(g_kh + src0 + row * Dd + cl * 8)
                            : (comp == 1) ? (const void*)(g_kl + src0 + row * Dd + cl * 8)
                                          : (const void*)(g_vf + src0 + row * Dd + cl * 8);
            cp16(bsm + comp * 8192 + SWZ(row * 128 + cl * 16), src);
        }
    };
    loadkv(0, 0); CP_COMMIT();
    loadkv(1, 1); CP_COMMIT();

    float oacc[8][4];
#pragma unroll
    for (int i = 0; i < 8; i++)
#pragma unroll
        for (int j = 0; j < 4; j++) oacc[i][j] = 0.f;
    float m0 = -1e30f, m1 = -1e30f, l0 = 0.f, l1 = 0.f;

    for (int c = 0; c < ntiles; c++) {
        CP_WAIT1();
        __syncthreads();
        const uint32_t kh = smb + 32768 + (c & 1) * 24576;
        const uint32_t kl = kh + 8192, vf = kh + 16384;

        // ---- S = Q K^T (bf16 3-term) ----
        float sacc[8][4];
#pragma unroll
        for (int i = 0; i < 8; i++)
#pragma unroll
            for (int j = 0; j < 4; j++) sacc[i][j] = 0.f;
#pragma unroll
        for (int k16 = 0; k16 < 4; k16++) {
            const int colb = k16 * 32 + (lane >> 4) * 16;
            uint32_t ah[4], al[4];
            ldsm4(ah, smb + SWZ((wm + (lane & 15)) * 128 + colb));
            ldsm4(al, smb + 16384 + SWZ((wm + (lane & 15)) * 128 + colb));
#pragma unroll
            for (int nt4 = 0; nt4 < 4; nt4++) {
                uint32_t kh4[4], kl4[4];
                uint32_t ra = SWZ((nt4 * 16 + (lane & 15)) * 128 + colb);
                ldsm4(kh4, kh + ra);
                ldsm4(kl4, kl + ra);
                uint32_t bh0[2] = {kh4[0], kh4[2]}, bh1[2] = {kh4[1], kh4[3]};
                uint32_t bl0[2] = {kl4[0], kl4[2]}, bl1[2] = {kl4[1], kl4[3]};
                mma16816(sacc[nt4 * 2 + 0], ah, bh0);
                mma16816(sacc[nt4 * 2 + 1], ah, bh1);
                mma16816(sacc[nt4 * 2 + 0], ah, bl0);
                mma16816(sacc[nt4 * 2 + 1], ah, bl1);
                mma16816(sacc[nt4 * 2 + 0], al, bh0);
                mma16816(sacc[nt4 * 2 + 1], al, bh1);
            }
        }

        // ---- causal mask (diagonal tiles only) ----
        if (c >= 2 * rb) {
#pragma unroll
            for (int nt = 0; nt < 8; nt++) {
                const int cg = c * 64 + nt * 8 + c2;
                if (cg > row0)     sacc[nt][0] = -1e30f;
                if (cg + 1 > row0) sacc[nt][1] = -1e30f;
                if (cg > row1)     sacc[nt][2] = -1e30f;
                if (cg + 1 > row1) sacc[nt][3] = -1e30f;
            }
        }

        // ---- register softmax (quad shuffles) ----
        {
            float mx0 = -1e30f, mx1 = -1e30f;
#pragma unroll
            for (int nt = 0; nt < 8; nt++) {
                mx0 = fmaxf(mx0, fmaxf(sacc[nt][0], sacc[nt][1]));
                mx1 = fmaxf(mx1, fmaxf(sacc[nt][2], sacc[nt][3]));
            }
            mx0 = fmaxf(mx0, __shfl_xor_sync(0xffffffffu, mx0, 1));
            mx0 = fmaxf(mx0, __shfl_xor_sync(0xffffffffu, mx0, 2));
            mx1 = fmaxf(mx1, __shfl_xor_sync(0xffffffffu, mx1, 1));
            mx1 = fmaxf(mx1, __shfl_xor_sync(0xffffffffu, mx1, 2));
            float mn0 = fmaxf(m0, mx0), mn1 = fmaxf(m1, mx1);
            float sc0 = expapx(m0 - mn0), sc1 = expapx(m1 - mn1);
            float s0 = 0.f, s1 = 0.f;
#pragma unroll
            for (int nt = 0; nt < 8; nt++) {
                float e0 = expapx(sacc[nt][0] - mn0);
                float e1 = expapx(sacc[nt][1] - mn0);
                float e2 = expapx(sacc[nt][2] - mn1);
                float e3 = expapx(sacc[nt][3] - mn1);
                sacc[nt][0] = e0; sacc[nt][1] = e1;
                sacc[nt][2] = e2; sacc[nt][3] = e3;
                s0 += e0 + e1; s1 += e2 + e3;
                oacc[nt][0] *= sc0; oacc[nt][1] *= sc0;
                oacc[nt][2] *= sc1; oacc[nt][3] *= sc1;
            }
            s0 += __shfl_xor_sync(0xffffffffu, s0, 1);
            s0 += __shfl_xor_sync(0xffffffffu, s0, 2);
            s1 += __shfl_xor_sync(0xffffffffu, s1, 1);
            s1 += __shfl_xor_sync(0xffffffffu, s1, 2);
            l0 = l0 * sc0 + s0; l1 = l1 * sc1 + s1;
            m0 = mn0; m1 = mn1;
        }

        // ---- O += P V (fp16 single-term) ----
#pragma unroll
        for (int kt = 0; kt < 4; kt++) {
            uint32_t ph[4] = {pkh2(sacc[2*kt][0],   sacc[2*kt][1]),
                              pkh2(sacc[2*kt][2],   sacc[2*kt][3]),
                              pkh2(sacc[2*kt+1][0], sacc[2*kt+1][1]),
                              pkh2(sacc[2*kt+1][2], sacc[2*kt+1][3])};
#pragma unroll
            for (int nt2 = 0; nt2 < 4; nt2++) {
                uint32_t ra = SWZ((kt * 16 + (lane & 15)) * 128 +
                                  nt2 * 32 + (lane >> 4) * 16);
                uint32_t v4[4];
                ldsm4t(v4, vf + ra);
                uint32_t b0[2] = {v4[0], v4[1]}, b1[2] = {v4[2], v4[3]};
                mmah(oacc[nt2 * 2 + 0], ph, b0);
                mmah(oacc[nt2 * 2 + 1], ph, b1);
            }
        }
        __syncthreads();
        if (c + 2 < ntiles) loadkv(c + 2, c & 1);
        CP_COMMIT();
    }

    // ---- finalize: O/l -> g_ox fp16 ----
    {
        float inv0 = 1.f / l0, inv1 = 1.f / l1;
        const size_t mg0 = (size_t)bb * Tt + row0;
#pragma unroll
        for (int nt = 0; nt < 8; nt++) {
            const int col = hh * 64 + nt * 8 + c2;
            *(uint32_t*)&g_ox[mg0 * 1024 + col] =
                pkh2(oacc[nt][0] * inv0, oacc[nt][1] * inv0);
            *(uint32_t*)&g_ox[(mg0 + 8) * 1024 + col] =
                pkh2(oacc[nt][2] * inv1, oacc[nt][3] * inv1);
        }
    }
}

// ---------------------------------------------------------------------------
extern "C" void kernel_launch(void* const* d_in, const int* in_sizes, int n_in,
                              void* d_out, int out_size) {
    const float* x  = (const float*)d_in[0];   // [2,2048,1024]
    const float* Wa = (const float*)d_in[1];   // [3072,1024]
    const float* Wp = (const float*)d_in[2];   // [1024,1024]
    float* y = (float*)d_out;                  // [2,2048,1024]

    static const int GSM = 65536;
    static const int ASM = 81920;
    cudaFuncSetAttribute((const void*)gemmqkv,
                         cudaFuncAttributeMaxDynamicSharedMemorySize, GSM);
    cudaFuncSetAttribute((const void*)gemmproj,
                         cudaFuncAttributeMaxDynamicSharedMemorySize, GSM);
    cudaFuncSetAttribute((const void*)attn_mma,
                         cudaFuncAttributeMaxDynamicSharedMemorySize, ASM);

    packk<0><<<4096, 256>>>(x);
    packk<1><<<3072, 256>>>(Wa);
    packk<2><<<1024, 256>>>(Wp);

    gemmqkv<<<dim3(24, 32), 256, GSM>>>();             // QKV (N=3072)

    attn_mma<<<dim3(16, 32), 256, ASM>>>();

    gemmproj<<<dim3(8, 32), 256, GSM>>>(y);            // proj (N=1024)
}

// round 14
// speedup vs baseline: 3.3596x; 1.0969x over previous
#include <cuda_runtime.h>
#include <cuda_bf16.h>
#include <cuda_fp16.h>
#include <math.h>
#include <stdint.h>

// Problem constants
#define Bq 2
#define Hh 16
#define Tt 2048
#define Cc 1024
#define Dd 64
#define KP 3072     // packed K (3x1024) for the bf16-split QK GEMM
#define NCH 48      // K chunks of 64 bf16 (QK GEMM)
#define NCHP 16     // K chunks of 64 fp16 (v / proj GEMMs, K=1024)

// Scratch (device globals: allocation-free). 16B alignment for cp.async.
__device__ __align__(16) __nv_bfloat16 g_qh[Bq*Hh*Tt*Dd];
__device__ __align__(16) __nv_bfloat16 g_ql[Bq*Hh*Tt*Dd];
__device__ __align__(16) __nv_bfloat16 g_kh[Bq*Hh*Tt*Dd];
__device__ __align__(16) __nv_bfloat16 g_kl[Bq*Hh*Tt*Dd];
__device__ __align__(16) __half       g_vf[Bq*Hh*Tt*Dd];   // V fp16 single
__device__ __align__(16) __nv_bfloat16 g_ax[4096*KP];   // packed x    [hi|hi|lo]
__device__ __align__(16) __half       g_xf[4096*1024];  // x fp16 (for V GEMM)
__device__ __align__(16) __nv_bfloat16 g_wa[2048*KP];   // W_attn q,k [hi|lo|hi]
__device__ __align__(16) __half       g_wvf[1024*1024]; // W_attn v rows fp16
__device__ __align__(16) __half       g_wpf[1024*1024]; // W_proj(view) fp16
__device__ __align__(16) __half       g_ox[4096*1024];  // O fp16 single

// ---------------------------------------------------------------------------
// Baseline-ISA helpers (sm_80+; valid on plain sm_103 target)
// ---------------------------------------------------------------------------
static __device__ __forceinline__ uint32_t s2u(const void* p) {
    uint32_t a;
    asm("{ .reg .u64 t; cvta.to.shared.u64 t, %1; cvt.u32.u64 %0, t; }"
        : "=r"(a) : "l"(p));
    return a;
}
#define SWZ(o) ((o) ^ (((o) >> 3) & 0x70))

static __device__ __forceinline__ void mma16816(float* c, const uint32_t* a,
                                                const uint32_t* b) {
    asm volatile(
        "mma.sync.aligned.m16n8k16.row.col.f32.bf16.bf16.f32 "
        "{%0,%1,%2,%3}, {%4,%5,%6,%7}, {%8,%9}, {%0,%1,%2,%3};"
        : "+f"(c[0]), "+f"(c[1]), "+f"(c[2]), "+f"(c[3])
        : "r"(a[0]), "r"(a[1]), "r"(a[2]), "r"(a[3]), "r"(b[0]), "r"(b[1]));
}
static __device__ __forceinline__ void mmah(float* c, const uint32_t* a,
                                            const uint32_t* b) {
    asm volatile(
        "mma.sync.aligned.m16n8k16.row.col.f32.f16.f16.f32 "
        "{%0,%1,%2,%3}, {%4,%5,%6,%7}, {%8,%9}, {%0,%1,%2,%3};"
        : "+f"(c[0]), "+f"(c[1]), "+f"(c[2]), "+f"(c[3])
        : "r"(a[0]), "r"(a[1]), "r"(a[2]), "r"(a[3]), "r"(b[0]), "r"(b[1]));
}
static __device__ __forceinline__ void ldsm4(uint32_t* r, uint32_t addr) {
    asm volatile("ldmatrix.sync.aligned.m8n8.x4.shared.b16 {%0,%1,%2,%3}, [%4];"
                 : "=r"(r[0]), "=r"(r[1]), "=r"(r[2]), "=r"(r[3]) : "r"(addr));
}
static __device__ __forceinline__ void ldsm4t(uint32_t* r, uint32_t addr) {
    asm volatile("ldmatrix.sync.aligned.m8n8.x4.trans.shared.b16 {%0,%1,%2,%3}, [%4];"
                 : "=r"(r[0]), "=r"(r[1]), "=r"(r[2]), "=r"(r[3]) : "r"(addr));
}
static __device__ __forceinline__ void cp16(uint32_t dst, const void* src) {
    asm volatile("cp.async.cg.shared.global [%0], [%1], 16;" :: "r"(dst), "l"(src));
}
#define CP_COMMIT() asm volatile("cp.async.commit_group;" ::: "memory")
#define CP_WAIT1()  asm volatile("cp.async.wait_group 1;" ::: "memory")

static __device__ __forceinline__ uint32_t pk2(float a, float b) {
    __nv_bfloat162 t = __floats2bfloat162_rn(a, b);
    return *reinterpret_cast<uint32_t*>(&t);
}
static __device__ __forceinline__ uint32_t pkh2(float a, float b) {
    __half2 t = __floats2half2_rn(a, b);
    return *reinterpret_cast<uint32_t*>(&t);
}
static __device__ __forceinline__ float bhi(float x) {
    return __bfloat162float(__float2bfloat16(x));
}

// e^x for x <= 0 via FMA-pipe poly (no MUFU). err ~2.4e-6 rel.
static __device__ __forceinline__ float expapx(float x) {
    float y = fmaxf(x, -87.0f) * 1.44269504f;
    float z = y + 12582912.0f;          // round-to-nearest int (magic)
    float r = z - 12582912.0f;
    float f = y - r;                    // f in [-0.5, 0.5]
    float p = 1.33335581e-3f;
    p = fmaf(p, f, 9.61812911e-3f);
    p = fmaf(p, f, 5.55041087e-2f);
    p = fmaf(p, f, 2.40226507e-1f);
    p = fmaf(p, f, 6.93147181e-1f);
    p = fmaf(p, f, 1.0f);
    return p * __int_as_float((__float_as_int(z) << 23) + 0x3F800000);
}

// ---------------------------------------------------------------------------
// Unified pack kernel. blockIdx ranges:
//   [0,4096):     x row     -> g_ax [hi|hi|lo] + g_xf fp16
//   [4096,6144):  W_attn qk -> g_wa [hi|lo|hi]
//   [6144,7168):  W_attn v  -> g_wvf fp16  (source row 2048+n)
//   [7168,8192):  W_proj(view) -> g_wpf fp16
// ---------------------------------------------------------------------------
__global__ __launch_bounds__(256)
void packall(const float* __restrict__ x, const float* __restrict__ Wa,
             const float* __restrict__ Wp) {
    const int b = blockIdx.x;
    const int c4 = threadIdx.x * 4;
    if (b < 4096) {
        const int m = b;
        float4 v = *(const float4*)(x + (size_t)m * 1024 + c4);
        float vv[4] = {v.x, v.y, v.z, v.w};
        union U { __nv_bfloat16 bb[4]; uint2 u; };
        U H, L;
#pragma unroll
        for (int j = 0; j < 4; j++) {
            H.bb[j] = __float2bfloat16(vv[j]);
            L.bb[j] = __float2bfloat16(vv[j] - __bfloat162float(H.bb[j]));
        }
        __nv_bfloat16* row = g_ax + (size_t)m * KP;
        *(uint2*)(row + c4) = H.u;
        *(uint2*)(row + 1024 + c4) = H.u;
        *(uint2*)(row + 2048 + c4) = L.u;
        *(uint2*)&g_xf[(size_t)m * 1024 + c4] =
            make_uint2(pkh2(v.x, v.y), pkh2(v.z, v.w));
    } else if (b < 6144) {
        const int m = b - 4096;
        float4 v = *(const float4*)(Wa + (size_t)m * 1024 + c4);
        float vv[4] = {v.x, v.y, v.z, v.w};
        union U { __nv_bfloat16 bb[4]; uint2 u; };
        U H, L;
#pragma unroll
        for (int j = 0; j < 4; j++) {
            H.bb[j] = __float2bfloat16(vv[j]);
            L.bb[j] = __float2bfloat16(vv[j] - __bfloat162float(H.bb[j]));
        }
        __nv_bfloat16* row = g_wa + (size_t)m * KP;
        *(uint2*)(row + c4) = H.u;
        *(uint2*)(row + 1024 + c4) = L.u;
        *(uint2*)(row + 2048 + c4) = H.u;
    } else if (b < 7168) {
        const int n = b - 6144;
        float4 v = *(const float4*)(Wa + (size_t)(2048 + n) * 1024 + c4);
        *(uint2*)&g_wvf[(size_t)n * 1024 + c4] =
            make_uint2(pkh2(v.x, v.y), pkh2(v.z, v.w));
    } else {
        const int m = b - 7168;
        float4 v = *(const float4*)(Wp + (((c4 >> 6) << 16) + (m << 6) + (c4 & 63)));
        *(uint2*)&g_wpf[(size_t)m * 1024 + c4] =
            make_uint2(pkh2(v.x, v.y), pkh2(v.z, v.w));
    }
}

// ---------------------------------------------------------------------------
// QK GEMM: bf16 3-term, K'=3072, N=2048. Epilogue writes q/k hi/lo bf16.
// ---------------------------------------------------------------------------
__global__ __launch_bounds__(256, 2)
void gemmqk() {
    extern __shared__ __align__(1024) char sm[];
    const uint32_t smb = s2u(sm);
    const int tid = threadIdx.x, wid = tid >> 5, lane = tid & 31;
    const int bm = blockIdx.y * 128, bn = blockIdx.x * 128;
    const int wm = (wid & 3) * 32, wn = (wid >> 2) * 64;

    auto load = [&](int c, int s) {
        const __nv_bfloat16* Ab = g_ax + (size_t)bm * KP + c * 64;
        const __nv_bfloat16* Wb = g_wa + (size_t)bn * KP + c * 64;
        uint32_t as = smb + s * 16384;
        uint32_t bs = smb + 32768 + s * 16384;
#pragma unroll
        for (int t = 0; t < 4; t++) {
            int idx = tid + t * 256;
            int row = idx >> 3, col = idx & 7;
            uint32_t so = SWZ(row * 128 + col * 16);
            cp16(as + so, Ab + (size_t)row * KP + col * 8);
            cp16(bs + so, Wb + (size_t)row * KP + col * 8);
        }
    };

    float acc[2][8][4];
#pragma unroll
    for (int i = 0; i < 2; i++)
#pragma unroll
        for (int j = 0; j < 8; j++)
#pragma unroll
            for (int q = 0; q < 4; q++) acc[i][j][q] = 0.f;

    load(0, 0); CP_COMMIT();
    load(1, 1); CP_COMMIT();

    for (int c = 0; c < NCH; c++) {
        CP_WAIT1();
        __syncthreads();
        const uint32_t ab = smb + (c & 1) * 16384;
        const uint32_t bb = smb + 32768 + (c & 1) * 16384;
#pragma unroll
        for (int k16 = 0; k16 < 4; k16++) {
            const int colb = k16 * 32 + (lane >> 4) * 16;
            uint32_t a[2][4], b4[4][4];
#pragma unroll
            for (int mt = 0; mt < 2; mt++) {
                int row = wm + mt * 16 + (lane & 15);
                ldsm4(a[mt], ab + SWZ(row * 128 + colb));
            }
#pragma unroll
            for (int nt2 = 0; nt2 < 4; nt2++) {
                int row = wn + nt2 * 16 + (lane & 15);
                ldsm4(b4[nt2], bb + SWZ(row * 128 + colb));
            }
#pragma unroll
            for (int mt = 0; mt < 2; mt++)
#pragma unroll
                for (int nt2 = 0; nt2 < 4; nt2++) {
                    uint32_t b0[2] = {b4[nt2][0], b4[nt2][2]};
                    uint32_t b1[2] = {b4[nt2][1], b4[nt2][3]};
                    mma16816(acc[mt][nt2 * 2 + 0], a[mt], b0);
                    mma16816(acc[mt][nt2 * 2 + 1], a[mt], b1);
                }
        }
        __syncthreads();
        if (c + 2 < NCH) load(c + 2, c & 1);
        CP_COMMIT();
    }

    const int r4 = lane >> 2, c2 = (lane & 3) * 2;
#pragma unroll
    for (int mt = 0; mt < 2; mt++) {
#pragma unroll
        for (int nt = 0; nt < 8; nt++) {
            const int m0 = bm + wm + mt * 16 + r4;
            const int n  = bn + wn + nt * 8 + c2;
            float2 v0 = make_float2(acc[mt][nt][0], acc[mt][nt][1]);
            float2 v1 = make_float2(acc[mt][nt][2], acc[mt][nt][3]);
            const int which = n >> 10, cc = n & 1023;
            const int h = cc >> 6, d = cc & 63;
            const int b = m0 >> 11, t0 = m0 & 2047;
            const size_t base = ((size_t)(b * Hh + h) * Tt + t0) * Dd + d;
            __nv_bfloat16* dh = which ? g_kh : g_qh;
            __nv_bfloat16* dl = which ? g_kl : g_ql;
            *(uint32_t*)&dh[base] = pk2(v0.x, v0.y);
            *(uint32_t*)&dl[base] = pk2(v0.x - bhi(v0.x), v0.y - bhi(v0.y));
            *(uint32_t*)&dh[base + 8 * Dd] = pk2(v1.x, v1.y);
            *(uint32_t*)&dl[base + 8 * Dd] =
                pk2(v1.x - bhi(v1.x), v1.y - bhi(v1.y));
        }
    }
}

// ---------------------------------------------------------------------------
// fp16 single-term GEMM, K=1024.
// MODE 0 (V): A=g_xf, W=g_wvf, epilogue scatters fp16 to g_vf.
// MODE 1 (proj): A=g_ox, W=g_wpf, epilogue writes fp32 out.
// ---------------------------------------------------------------------------
template<int MODE>
__global__ __launch_bounds__(256, 2)
void gemmh(float* __restrict__ out) {
    extern __shared__ __align__(1024) char sm[];
    const uint32_t smb = s2u(sm);
    const int tid = threadIdx.x, wid = tid >> 5, lane = tid & 31;
    const int bm = blockIdx.y * 128, bn = blockIdx.x * 128;
    const int wm = (wid & 3) * 32, wn = (wid >> 2) * 64;

    const __half* __restrict__ A = MODE ? g_ox : g_xf;
    const __half* __restrict__ W = MODE ? g_wpf : g_wvf;

    auto load = [&](int c, int s) {
        const __half* Ab = A + (size_t)bm * 1024 + c * 64;
        const __half* Wb = W + (size_t)bn * 1024 + c * 64;
        uint32_t as = smb + s * 16384;
        uint32_t bs = smb + 32768 + s * 16384;
#pragma unroll
        for (int t = 0; t < 4; t++) {
            int idx = tid + t * 256;
            int row = idx >> 3, col = idx & 7;
            uint32_t so = SWZ(row * 128 + col * 16);
            cp16(as + so, Ab + (size_t)row * 1024 + col * 8);
            cp16(bs + so, Wb + (size_t)row * 1024 + col * 8);
        }
    };

    float acc[2][8][4];
#pragma unroll
    for (int i = 0; i < 2; i++)
#pragma unroll
        for (int j = 0; j < 8; j++)
#pragma unroll
            for (int q = 0; q < 4; q++) acc[i][j][q] = 0.f;

    load(0, 0); CP_COMMIT();
    load(1, 1); CP_COMMIT();

    for (int c = 0; c < NCHP; c++) {
        CP_WAIT1();
        __syncthreads();
        const uint32_t ab = smb + (c & 1) * 16384;
        const uint32_t bb = smb + 32768 + (c & 1) * 16384;
#pragma unroll
        for (int k16 = 0; k16 < 4; k16++) {
            const int colb = k16 * 32 + (lane >> 4) * 16;
            uint32_t a[2][4], b4[4][4];
#pragma unroll
            for (int mt = 0; mt < 2; mt++) {
                int row = wm + mt * 16 + (lane & 15);
                ldsm4(a[mt], ab + SWZ(row * 128 + colb));
            }
#pragma unroll
            for (int nt2 = 0; nt2 < 4; nt2++) {
                int row = wn + nt2 * 16 + (lane & 15);
                ldsm4(b4[nt2], bb + SWZ(row * 128 + colb));
            }
#pragma unroll
            for (int mt = 0; mt < 2; mt++)
#pragma unroll
                for (int nt2 = 0; nt2 < 4; nt2++) {
                    uint32_t b0[2] = {b4[nt2][0], b4[nt2][2]};
                    uint32_t b1[2] = {b4[nt2][1], b4[nt2][3]};
                    mmah(acc[mt][nt2 * 2 + 0], a[mt], b0);
                    mmah(acc[mt][nt2 * 2 + 1], a[mt], b1);
                }
        }
        __syncthreads();
        if (c + 2 < NCHP) load(c + 2, c & 1);
        CP_COMMIT();
    }

    const int r4 = lane >> 2, c2 = (lane & 3) * 2;
#pragma unroll
    for (int mt = 0; mt < 2; mt++) {
#pragma unroll
        for (int nt = 0; nt < 8; nt++) {
            const int m0 = bm + wm + mt * 16 + r4;
            const int n  = bn + wn + nt * 8 + c2;
            if (MODE == 0) {
                const int h = n >> 6, d = n & 63;
                const int b = m0 >> 11, t0 = m0 & 2047;
                const size_t base = ((size_t)(b * Hh + h) * Tt + t0) * Dd + d;
                *(uint32_t*)&g_vf[base] = pkh2(acc[mt][nt][0], acc[mt][nt][1]);
                *(uint32_t*)&g_vf[base + 8 * Dd] =
                    pkh2(acc[mt][nt][2], acc[mt][nt][3]);
            } else {
                *(float2*)&out[(size_t)m0 * Cc + n] =
                    make_float2(acc[mt][nt][0], acc[mt][nt][1]);
                *(float2*)&out[(size_t)(m0 + 8) * Cc + n] =
                    make_float2(acc[mt][nt][2], acc[mt][nt][3]);
            }
        }
    }
}

// ---------------------------------------------------------------------------
// FA2-style attention: QK^T bf16 3-term, PV fp16 single-term. (unchanged R13)
// Smem: Qh 0, Ql 16384; KV stage s at 32768+s*24576 {Kh +0, Kl +8192, Vf +16384}
// ---------------------------------------------------------------------------
__global__ __launch_bounds__(256, 2)
void attn_mma() {
    extern __shared__ __align__(1024) char sma[];
    const uint32_t smb = s2u(sma);
    const int rb = 15 - (int)blockIdx.x;    // heavy row-blocks first
    const int bh = blockIdx.y;
    const int r0g = rb * 128;
    const int tid = threadIdx.x, wid = tid >> 5, lane = tid & 31;
    const int wm = wid * 16;
    const int r4 = lane >> 2, c2 = (lane & 3) * 2;
    const int row0 = r0g + wm + r4, row1 = row0 + 8;
    const int bb = bh >> 4, hh = bh & 15;
    const size_t hbase = (size_t)bh * (Tt * Dd);

    // Q tiles (hi/lo) -> smem once
    {
        const __nv_bfloat16* qs[2] = {g_qh, g_ql};
#pragma unroll
        for (int t = 0; t < 8; t++) {
            int comp = t >> 2;
            int q = ((t & 3) << 8) + tid;
            int row = q >> 3, cl = q & 7;
            cp16(smb + comp * 16384 + SWZ(row * 128 + cl * 16),
                 qs[comp] + hbase + (size_t)(r0g + row) * Dd + cl * 8);
        }
        CP_COMMIT();
    }

    const int ntiles = 2 * rb + 2;
    auto loadkv = [&](int c, int s) {
        uint32_t bsm = smb + 32768 + s * 24576;
        size_t src0 = hbase + (size_t)c * 64 * Dd;
#pragma unroll
        for (int t = 0; t < 6; t++) {
            int comp = t >> 1;
            int q = ((t & 1) << 8) + tid;
            int row = q >> 3, cl = q & 7;
            const void* src = (comp == 0) ? (const void*)(g_kh + src0 + row * Dd + cl * 8)
                            : (comp == 1) ? (const void*)(g_kl + src0 + row * Dd + cl * 8)
                                          : (const void*)(g_vf + src0 + row * Dd + cl * 8);
            cp16(bsm + comp * 8192 + SWZ(row * 128 + cl * 16), src);
        }
    };
    loadkv(0, 0); CP_COMMIT();
    loadkv(1, 1); CP_COMMIT();

    float oacc[8][4];
#pragma unroll
    for (int i = 0; i < 8; i++)
#pragma unroll
        for (int j = 0; j < 4; j++) oacc[i][j] = 0.f;
    float m0 = -1e30f, m1 = -1e30f, l0 = 0.f, l1 = 0.f;

    for (int c = 0; c < ntiles; c++) {
        CP_WAIT1();
        __syncthreads();
        const uint32_t kh = smb + 32768 + (c & 1) * 24576;
        const uint32_t kl = kh + 8192, vf = kh + 16384;

        // ---- S = Q K^T (bf16 3-term) ----
        float sacc[8][4];
#pragma unroll
        for (int i = 0; i < 8; i++)
#pragma unroll
            for (int j = 0; j < 4; j++) sacc[i][j] = 0.f;
#pragma unroll
        for (int k16 = 0; k16 < 4; k16++) {
            const int colb = k16 * 32 + (lane >> 4) * 16;
            uint32_t ah[4], al[4];
            ldsm4(ah, smb + SWZ((wm + (lane & 15)) * 128 + colb));
            ldsm4(al, smb + 16384 + SWZ((wm + (lane & 15)) * 128 + colb));
#pragma unroll
            for (int nt4 = 0; nt4 < 4; nt4++) {
                uint32_t kh4[4], kl4[4];
                uint32_t ra = SWZ((nt4 * 16 + (lane & 15)) * 128 + colb);
                ldsm4(kh4, kh + ra);
                ldsm4(kl4, kl + ra);
                uint32_t bh0[2] = {kh4[0], kh4[2]}, bh1[2] = {kh4[1], kh4[3]};
                uint32_t bl0[2] = {kl4[0], kl4[2]}, bl1[2] = {kl4[1], kl4[3]};
                mma16816(sacc[nt4 * 2 + 0], ah, bh0);
                mma16816(sacc[nt4 * 2 + 1], ah, bh1);
                mma16816(sacc[nt4 * 2 + 0], ah, bl0);
                mma16816(sacc[nt4 * 2 + 1], ah, bl1);
                mma16816(sacc[nt4 * 2 + 0], al, bh0);
                mma16816(sacc[nt4 * 2 + 1], al, bh1);
            }
        }

        // ---- causal mask (diagonal tiles only) ----
        if (c >= 2 * rb) {
#pragma unroll
            for (int nt = 0; nt < 8; nt++) {
                const int cg = c * 64 + nt * 8 + c2;
                if (cg > row0)     sacc[nt][0] = -1e30f;
                if (cg + 1 > row0) sacc[nt][1] = -1e30f;
                if (cg > row1)     sacc[nt][2] = -1e30f;
                if (cg + 1 > row1) sacc[nt][3] = -1e30f;
            }
        }

        // ---- register softmax (quad shuffles) ----
        {
            float mx0 = -1e30f, mx1 = -1e30f;
#pragma unroll
            for (int nt = 0; nt < 8; nt++) {
                mx0 = fmaxf(mx0, fmaxf(sacc[nt][0], sacc[nt][1]));
                mx1 = fmaxf(mx1, fmaxf(sacc[nt][2], sacc[nt][3]));
            }
            mx0 = fmaxf(mx0, __shfl_xor_sync(0xffffffffu, mx0, 1));
            mx0 = fmaxf(mx0, __shfl_xor_sync(0xffffffffu, mx0, 2));
            mx1 = fmaxf(mx1, __shfl_xor_sync(0xffffffffu, mx1, 1));
            mx1 = fmaxf(mx1, __shfl_xor_sync(0xffffffffu, mx1, 2));
            float mn0 = fmaxf(m0, mx0), mn1 = fmaxf(m1, mx1);
            float sc0 = expapx(m0 - mn0), sc1 = expapx(m1 - mn1);
            float s0 = 0.f, s1 = 0.f;
#pragma unroll
            for (int nt = 0; nt < 8; nt++) {
                float e0 = expapx(sacc[nt][0] - mn0);
                float e1 = expapx(sacc[nt][1] - mn0);
                float e2 = expapx(sacc[nt][2] - mn1);
                float e3 = expapx(sacc[nt][3] - mn1);
                sacc[nt][0] = e0; sacc[nt][1] = e1;
                sacc[nt][2] = e2; sacc[nt][3] = e3;
                s0 += e0 + e1; s1 += e2 + e3;
                oacc[nt][0] *= sc0; oacc[nt][1] *= sc0;
                oacc[nt][2] *= sc1; oacc[nt][3] *= sc1;
            }
            s0 += __shfl_xor_sync(0xffffffffu, s0, 1);
            s0 += __shfl_xor_sync(0xffffffffu, s0, 2);
            s1 += __shfl_xor_sync(0xffffffffu, s1, 1);
            s1 += __shfl_xor_sync(0xffffffffu, s1, 2);
            l0 = l0 * sc0 + s0; l1 = l1 * sc1 + s1;
            m0 = mn0; m1 = mn1;
        }

        // ---- O += P V (fp16 single-term) ----
#pragma unroll
        for (int kt = 0; kt < 4; kt++) {
            uint32_t ph[4] = {pkh2(sacc[2*kt][0],   sacc[2*kt][1]),
                              pkh2(sacc[2*kt][2],   sacc[2*kt][3]),
                              pkh2(sacc[2*kt+1][0], sacc[2*kt+1][1]),
                              pkh2(sacc[2*kt+1][2], sacc[2*kt+1][3])};
#pragma unroll
            for (int nt2 = 0; nt2 < 4; nt2++) {
                uint32_t ra = SWZ((kt * 16 + (lane & 15)) * 128 +
                                  nt2 * 32 + (lane >> 4) * 16);
                uint32_t v4[4];
                ldsm4t(v4, vf + ra);
                uint32_t b0[2] = {v4[0], v4[1]}, b1[2] = {v4[2], v4[3]};
                mmah(oacc[nt2 * 2 + 0], ph, b0);
                mmah(oacc[nt2 * 2 + 1], ph, b1);
            }
        }
        __syncthreads();
        if (c + 2 < ntiles) loadkv(c + 2, c & 1);
        CP_COMMIT();
    }

    // ---- finalize: O/l -> g_ox fp16 ----
    {
        float inv0 = 1.f / l0, inv1 = 1.f / l1;
        const size_t mg0 = (size_t)bb * Tt + row0;
#pragma unroll
        for (int nt = 0; nt < 8; nt++) {
            const int col = hh * 64 + nt * 8 + c2;
            *(uint32_t*)&g_ox[mg0 * 1024 + col] =
                pkh2(oacc[nt][0] * inv0, oacc[nt][1] * inv0);
            *(uint32_t*)&g_ox[(mg0 + 8) * 1024 + col] =
                pkh2(oacc[nt][2] * inv1, oacc[nt][3] * inv1);
        }
    }
}

// ---------------------------------------------------------------------------
extern "C" void kernel_launch(void* const* d_in, const int* in_sizes, int n_in,
                              void* d_out, int out_size) {
    const float* x  = (const float*)d_in[0];   // [2,2048,1024]
    const float* Wa = (const float*)d_in[1];   // [3072,1024]
    const float* Wp = (const float*)d_in[2];   // [1024,1024]
    float* y = (float*)d_out;                  // [2,2048,1024]

    static const int GSM = 65536;
    static const int ASM = 81920;
    cudaFuncSetAttribute((const void*)gemmqk,
                         cudaFuncAttributeMaxDynamicSharedMemorySize, GSM);
    cudaFuncSetAttribute((const void*)gemmh<0>,
                         cudaFuncAttributeMaxDynamicSharedMemorySize, GSM);
    cudaFuncSetAttribute((const void*)gemmh<1>,
                         cudaFuncAttributeMaxDynamicSharedMemorySize, GSM);
    cudaFuncSetAttribute((const void*)attn_mma,
                         cudaFuncAttributeMaxDynamicSharedMemorySize, ASM);

    packall<<<8192, 256>>>(x, Wa, Wp);

    gemmqk<<<dim3(16, 32), 256, GSM>>>();              // q,k (N=2048)
    gemmh<0><<<dim3(8, 32), 256, GSM>>>(nullptr);      // v   (N=1024, fp16)

    attn_mma<<<dim3(16, 32), 256, ASM>>>();

    gemmh<1><<<dim3(8, 32), 256, GSM>>>(y);            // proj (N=1024, fp16)
}

// round 17
// speedup vs baseline: 3.3895x; 1.0089x over previous
#include <cuda_runtime.h>
#include <cuda_bf16.h>
#include <cuda_fp16.h>
#include <math.h>
#include <stdint.h>

// Problem constants
#define Bq 2
#define Hh 16
#define Tt 2048
#define Cc 1024
#define Dd 64
#define KP 3072     // packed K (3x1024) for the bf16-split QK GEMM
#define NCH 48      // K chunks of 64 bf16 (QK GEMM)
#define NCHP 16     // K chunks of 64 fp16 (v / proj GEMMs, K=1024)

// Scratch (device globals: allocation-free). 16B alignment for cp.async.
__device__ __align__(16) __nv_bfloat16 g_qh[Bq*Hh*Tt*Dd];  // q*log2e hi
__device__ __align__(16) __nv_bfloat16 g_ql[Bq*Hh*Tt*Dd];  // q*log2e lo
__device__ __align__(16) __nv_bfloat16 g_kh[Bq*Hh*Tt*Dd];
__device__ __align__(16) __nv_bfloat16 g_kl[Bq*Hh*Tt*Dd];
__device__ __align__(16) __half       g_vf[Bq*Hh*Tt*Dd];   // V fp16 single
__device__ __align__(16) __nv_bfloat16 g_ax[4096*KP];   // packed x    [hi|hi|lo]
__device__ __align__(16) __half       g_xf[4096*1024];  // x fp16 (for V GEMM)
__device__ __align__(16) __nv_bfloat16 g_wa[2048*KP];   // W_attn q,k [hi|lo|hi]
__device__ __align__(16) __half       g_wvf[1024*1024]; // W_attn v rows fp16
__device__ __align__(16) __half       g_wpf[1024*1024]; // W_proj(view) fp16
__device__ __align__(16) __half       g_ox[4096*1024];  // O fp16 single

// ---------------------------------------------------------------------------
// Baseline-ISA helpers (sm_80+; valid on plain sm_103 target)
// ---------------------------------------------------------------------------
static __device__ __forceinline__ uint32_t s2u(const void* p) {
    uint32_t a;
    asm("{ .reg .u64 t; cvta.to.shared.u64 t, %1; cvt.u32.u64 %0, t; }"
        : "=r"(a) : "l"(p));
    return a;
}
#define SWZ(o) ((o) ^ (((o) >> 3) & 0x70))

static __device__ __forceinline__ void mma16816(float* c, const uint32_t* a,
                                                const uint32_t* b) {
    asm volatile(
        "mma.sync.aligned.m16n8k16.row.col.f32.bf16.bf16.f32 "
        "{%0,%1,%2,%3}, {%4,%5,%6,%7}, {%8,%9}, {%0,%1,%2,%3};"
        : "+f"(c[0]), "+f"(c[1]), "+f"(c[2]), "+f"(c[3])
        : "r"(a[0]), "r"(a[1]), "r"(a[2]), "r"(a[3]), "r"(b[0]), "r"(b[1]));
}
static __device__ __forceinline__ void mmah(float* c, const uint32_t* a,
                                            const uint32_t* b) {
    asm volatile(
        "mma.sync.aligned.m16n8k16.row.col.f32.f16.f16.f32 "
        "{%0,%1,%2,%3}, {%4,%5,%6,%7}, {%8,%9}, {%0,%1,%2,%3};"
        : "+f"(c[0]), "+f"(c[1]), "+f"(c[2]), "+f"(c[3])
        : "r"(a[0]), "r"(a[1]), "r"(a[2]), "r"(a[3]), "r"(b[0]), "r"(b[1]));
}
static __device__ __forceinline__ void ldsm4(uint32_t* r, uint32_t addr) {
    asm volatile("ldmatrix.sync.aligned.m8n8.x4.shared.b16 {%0,%1,%2,%3}, [%4];"
                 : "=r"(r[0]), "=r"(r[1]), "=r"(r[2]), "=r"(r[3]) : "r"(addr));
}
static __device__ __forceinline__ void ldsm4t(uint32_t* r, uint32_t addr) {
    asm volatile("ldmatrix.sync.aligned.m8n8.x4.trans.shared.b16 {%0,%1,%2,%3}, [%4];"
                 : "=r"(r[0]), "=r"(r[1]), "=r"(r[2]), "=r"(r[3]) : "r"(addr));
}
static __device__ __forceinline__ void cp16(uint32_t dst, const void* src) {
    asm volatile("cp.async.cg.shared.global [%0], [%1], 16;" :: "r"(dst), "l"(src));
}
#define CP_COMMIT() asm volatile("cp.async.commit_group;" ::: "memory")
#define CP_WAIT1()  asm volatile("cp.async.wait_group 1;" ::: "memory")

static __device__ __forceinline__ uint32_t pk2(float a, float b) {
    __nv_bfloat162 t = __floats2bfloat162_rn(a, b);
    return *reinterpret_cast<uint32_t*>(&t);
}
static __device__ __forceinline__ uint32_t pkh2(float a, float b) {
    __half2 t = __floats2half2_rn(a, b);
    return *reinterpret_cast<uint32_t*>(&t);
}
static __device__ __forceinline__ float bhi(float x) {
    return __bfloat162float(__float2bfloat16(x));
}

// 2^x for x <= 0 via FMA-pipe poly (no MUFU). Deg-4, err ~4e-5 rel.
static __device__ __forceinline__ float exp2apx(float x) {
    float y = fmaxf(x, -126.0f);
    float z = y + 12582912.0f;          // round-to-nearest int (magic)
    float f = y - (z - 12582912.0f);    // f in [-0.5, 0.5]
    float p = 9.61812911e-3f;
    p = fmaf(p, f, 5.55041087e-2f);
    p = fmaf(p, f, 2.40226507e-1f);
    p = fmaf(p, f, 6.93147181e-1f);
    p = fmaf(p, f, 1.0f);
    return p * __int_as_float((__float_as_int(z) << 23) + 0x3F800000);
}

// ---------------------------------------------------------------------------
// Unified pack kernel. blockIdx ranges:
//   [0,4096):     x row     -> g_ax [hi|hi|lo] + g_xf fp16
//   [4096,6144):  W_attn qk -> g_wa [hi|lo|hi]
//   [6144,7168):  W_attn v  -> g_wvf fp16  (source row 2048+n)
//   [7168,8192):  W_proj(view) -> g_wpf fp16
// ---------------------------------------------------------------------------
__global__ __launch_bounds__(256)
void packall(const float* __restrict__ x, const float* __restrict__ Wa,
             const float* __restrict__ Wp) {
    const int b = blockIdx.x;
    const int c4 = threadIdx.x * 4;
    if (b < 4096) {
        const int m = b;
        float4 v = *(const float4*)(x + (size_t)m * 1024 + c4);
        float vv[4] = {v.x, v.y, v.z, v.w};
        union U { __nv_bfloat16 bb[4]; uint2 u; };
        U H, L;
#pragma unroll
        for (int j = 0; j < 4; j++) {
            H.bb[j] = __float2bfloat16(vv[j]);
            L.bb[j] = __float2bfloat16(vv[j] - __bfloat162float(H.bb[j]));
        }
        __nv_bfloat16* row = g_ax + (size_t)m * KP;
        *(uint2*)(row + c4) = H.u;
        *(uint2*)(row + 1024 + c4) = H.u;
        *(uint2*)(row + 2048 + c4) = L.u;
        *(uint2*)&g_xf[(size_t)m * 1024 + c4] =
            make_uint2(pkh2(v.x, v.y), pkh2(v.z, v.w));
    } else if (b < 6144) {
        const int m = b - 4096;
        float4 v = *(const float4*)(Wa + (size_t)m * 1024 + c4);
        float vv[4] = {v.x, v.y, v.z, v.w};
        union U { __nv_bfloat16 bb[4]; uint2 u; };
        U H, L;
#pragma unroll
        for (int j = 0; j < 4; j++) {
            H.bb[j] = __float2bfloat16(vv[j]);
            L.bb[j] = __float2bfloat16(vv[j] - __bfloat162float(H.bb[j]));
        }
        __nv_bfloat16* row = g_wa + (size_t)m * KP;
        *(uint2*)(row + c4) = H.u;
        *(uint2*)(row + 1024 + c4) = L.u;
        *(uint2*)(row + 2048 + c4) = H.u;
    } else if (b < 7168) {
        const int n = b - 6144;
        float4 v = *(const float4*)(Wa + (size_t)(2048 + n) * 1024 + c4);
        *(uint2*)&g_wvf[(size_t)n * 1024 + c4] =
            make_uint2(pkh2(v.x, v.y), pkh2(v.z, v.w));
    } else {
        const int m = b - 7168;
        float4 v = *(const float4*)(Wp + (((c4 >> 6) << 16) + (m << 6) + (c4 & 63)));
        *(uint2*)&g_wpf[(size_t)m * 1024 + c4] =
            make_uint2(pkh2(v.x, v.y), pkh2(v.z, v.w));
    }
}

// ---------------------------------------------------------------------------
// QK GEMM: bf16 3-term, K'=3072, N=2048. 3-stage pipeline, single sync/iter.
// Epilogue writes q*log2e / k hi-lo bf16.
// Smem: stage s at s*32768 {A +0, B +16384}. Total 98304.
// ---------------------------------------------------------------------------
__global__ __launch_bounds__(256, 2)
void gemmqk() {
    extern __shared__ __align__(1024) char sm[];
    const uint32_t smb = s2u(sm);
    const int tid = threadIdx.x, wid = tid >> 5, lane = tid & 31;
    const int bm = blockIdx.y * 128, bn = blockIdx.x * 128;
    const int wm = (wid & 3) * 32, wn = (wid >> 2) * 64;

    auto load = [&](int c, int s) {
        const __nv_bfloat16* Ab = g_ax + (size_t)bm * KP + c * 64;
        const __nv_bfloat16* Wb = g_wa + (size_t)bn * KP + c * 64;
        uint32_t as = smb + s * 32768;
        uint32_t bs = as + 16384;
#pragma unroll
        for (int t = 0; t < 4; t++) {
            int idx = tid + t * 256;
            int row = idx >> 3, col = idx & 7;
            uint32_t so = SWZ(row * 128 + col * 16);
            cp16(as + so, Ab + (size_t)row * KP + col * 8);
            cp16(bs + so, Wb + (size_t)row * KP + col * 8);
        }
    };

    float acc[2][8][4];
#pragma unroll
    for (int i = 0; i < 2; i++)
#pragma unroll
        for (int j = 0; j < 8; j++)
#pragma unroll
            for (int q = 0; q < 4; q++) acc[i][j][q] = 0.f;

    load(0, 0); CP_COMMIT();
    load(1, 1); CP_COMMIT();

    for (int c = 0; c < NCH; c++) {
        CP_WAIT1();
        __syncthreads();
        if (c + 2 < NCH) load(c + 2, (c + 2) % 3);
        CP_COMMIT();
        const uint32_t ab = smb + (c % 3) * 32768;
        const uint32_t bb = ab + 16384;
#pragma unroll
        for (int k16 = 0; k16 < 4; k16++) {
            const int colb = k16 * 32 + (lane >> 4) * 16;
            uint32_t a[2][4], b4[4][4];
#pragma unroll
            for (int mt = 0; mt < 2; mt++) {
                int row = wm + mt * 16 + (lane & 15);
                ldsm4(a[mt], ab + SWZ(row * 128 + colb));
            }
#pragma unroll
            for (int nt2 = 0; nt2 < 4; nt2++) {
                int row = wn + nt2 * 16 + (lane & 15);
                ldsm4(b4[nt2], bb + SWZ(row * 128 + colb));
            }
#pragma unroll
            for (int mt = 0; mt < 2; mt++)
#pragma unroll
                for (int nt2 = 0; nt2 < 4; nt2++) {
                    uint32_t b0[2] = {b4[nt2][0], b4[nt2][2]};
                    uint32_t b1[2] = {b4[nt2][1], b4[nt2][3]};
                    mma16816(acc[mt][nt2 * 2 + 0], a[mt], b0);
                    mma16816(acc[mt][nt2 * 2 + 1], a[mt], b1);
                }
        }
    }

    const int r4 = lane >> 2, c2 = (lane & 3) * 2;
#pragma unroll
    for (int mt = 0; mt < 2; mt++) {
#pragma unroll
        for (int nt = 0; nt < 8; nt++) {
            const int m0 = bm + wm + mt * 16 + r4;
            const int n  = bn + wn + nt * 8 + c2;
            const int which = n >> 10, cc = n & 1023;
            const int h = cc >> 6, d = cc & 63;
            const int b = m0 >> 11, t0 = m0 & 2047;
            const size_t base = ((size_t)(b * Hh + h) * Tt + t0) * Dd + d;
            const float sc = which ? 1.0f : 1.44269504f;   // q scaled by log2e
            float2 v0 = make_float2(acc[mt][nt][0] * sc, acc[mt][nt][1] * sc);
            float2 v1 = make_float2(acc[mt][nt][2] * sc, acc[mt][nt][3] * sc);
            __nv_bfloat16* dh = which ? g_kh : g_qh;
            __nv_bfloat16* dl = which ? g_kl : g_ql;
            *(uint32_t*)&dh[base] = pk2(v0.x, v0.y);
            *(uint32_t*)&dl[base] = pk2(v0.x - bhi(v0.x), v0.y - bhi(v0.y));
            *(uint32_t*)&dh[base + 8 * Dd] = pk2(v1.x, v1.y);
            *(uint32_t*)&dl[base + 8 * Dd] =
                pk2(v1.x - bhi(v1.x), v1.y - bhi(v1.y));
        }
    }
}

// ---------------------------------------------------------------------------
// fp16 single-term GEMM, K=1024. 3-stage pipeline, single sync/iter.
// MODE 0 (V): A=g_xf, W=g_wvf, epilogue scatters fp16 to g_vf.
// MODE 1 (proj): A=g_ox, W=g_wpf, epilogue writes fp32 out.
// ---------------------------------------------------------------------------
template<int MODE>
__global__ __launch_bounds__(256, 2)
void gemmh(float* __restrict__ out) {
    extern __shared__ __align__(1024) char sm[];
    const uint32_t smb = s2u(sm);
    const int tid = threadIdx.x, wid = tid >> 5, lane = tid & 31;
    const int bm = blockIdx.y * 128, bn = blockIdx.x * 128;
    const int wm = (wid & 3) * 32, wn = (wid >> 2) * 64;

    const __half* __restrict__ A = MODE ? g_ox : g_xf;
    const __half* __restrict__ W = MODE ? g_wpf : g_wvf;

    auto load = [&](int c, int s) {
        const __half* Ab = A + (size_t)bm * 1024 + c * 64;
        const __half* Wb = W + (size_t)bn * 1024 + c * 64;
        uint32_t as = smb + s * 32768;
        uint32_t bs = as + 16384;
#pragma unroll
        for (int t = 0; t < 4; t++) {
            int idx = tid + t * 256;
            int row = idx >> 3, col = idx & 7;
            uint32_t so = SWZ(row * 128 + col * 16);
            cp16(as + so, Ab + (size_t)row * 1024 + col * 8);
            cp16(bs + so, Wb + (size_t)row * 1024 + col * 8);
        }
    };

    float acc[2][8][4];
#pragma unroll
    for (int i = 0; i < 2; i++)
#pragma unroll
        for (int j = 0; j < 8; j++)
#pragma unroll
            for (int q = 0; q < 4; q++) acc[i][j][q] = 0.f;

    load(0, 0); CP_COMMIT();
    load(1, 1); CP_COMMIT();

    for (int c = 0; c < NCHP; c++) {
        CP_WAIT1();
        __syncthreads();
        if (c + 2 < NCHP) load(c + 2, (c + 2) % 3);
        CP_COMMIT();
        const uint32_t ab = smb + (c % 3) * 32768;
        const uint32_t bb = ab + 16384;
#pragma unroll
        for (int k16 = 0; k16 < 4; k16++) {
            const int colb = k16 * 32 + (lane >> 4) * 16;
            uint32_t a[2][4], b4[4][4];
#pragma unroll
            for (int mt = 0; mt < 2; mt++) {
                int row = wm + mt * 16 + (lane & 15);
                ldsm4(a[mt], ab + SWZ(row * 128 + colb));
            }
#pragma unroll
            for (int nt2 = 0; nt2 < 4; nt2++) {
                int row = wn + nt2 * 16 + (lane & 15);
                ldsm4(b4[nt2], bb + SWZ(row * 128 + colb));
            }
#pragma unroll
            for (int mt = 0; mt < 2; mt++)
#pragma unroll
                for (int nt2 = 0; nt2 < 4; nt2++) {
                    uint32_t b0[2] = {b4[nt2][0], b4[nt2][2]};
                    uint32_t b1[2] = {b4[nt2][1], b4[nt2][3]};
                    mmah(acc[mt][nt2 * 2 + 0], a[mt], b0);
                    mmah(acc[mt][nt2 * 2 + 1], a[mt], b1);
                }
        }
    }

    const int r4 = lane >> 2, c2 = (lane & 3) * 2;
#pragma unroll
    for (int mt = 0; mt < 2; mt++) {
#pragma unroll
        for (int nt = 0; nt < 8; nt++) {
            const int m0 = bm + wm + mt * 16 + r4;
            const int n  = bn + wn + nt * 8 + c2;
            if (MODE == 0) {
                const int h = n >> 6, d = n & 63;
                const int b = m0 >> 11, t0 = m0 & 2047;
                const size_t base = ((size_t)(b * Hh + h) * Tt + t0) * Dd + d;
                *(uint32_t*)&g_vf[base] = pkh2(acc[mt][nt][0], acc[mt][nt][1]);
                *(uint32_t*)&g_vf[base + 8 * Dd] =
                    pkh2(acc[mt][nt][2], acc[mt][nt][3]);
            } else {
                *(float2*)&out[(size_t)m0 * Cc + n] =
                    make_float2(acc[mt][nt][0], acc[mt][nt][1]);
                *(float2*)&out[(size_t)(m0 + 8) * Cc + n] =
                    make_float2(acc[mt][nt][2], acc[mt][nt][3]);
            }
        }
    }
}

// ---------------------------------------------------------------------------
// FA2-style attention: QK^T bf16 3-term (log2 domain), PV fp16 single-term.
// 3-stage KV pipeline, single sync/iter, exp2 poly softmax.
// Smem: Qh 0, Ql 16384; KV stage s at 32768+s*24576 {Kh +0, Kl +8192, Vf +16384}
// Total 106496.
// ---------------------------------------------------------------------------
__global__ __launch_bounds__(256, 2)
void attn_mma() {
    extern __shared__ __align__(1024) char sma[];
    const uint32_t smb = s2u(sma);
    const int rb = 15 - (int)blockIdx.x;    // heavy row-blocks first
    const int bh = blockIdx.y;
    const int r0g = rb * 128;
    const int tid = threadIdx.x, wid = tid >> 5, lane = tid & 31;
    const int wm = wid * 16;
    const int r4 = lane >> 2, c2 = (lane & 3) * 2;
    const int row0 = r0g + wm + r4, row1 = row0 + 8;
    const int bb = bh >> 4, hh = bh & 15;
    const size_t hbase = (size_t)bh * (Tt * Dd);

    const int ntiles = 2 * rb + 2;
    auto loadkv = [&](int c, int s) {
        uint32_t bsm = smb + 32768 + s * 24576;
        size_t src0 = hbase + (size_t)c * 64 * Dd;
#pragma unroll
        for (int t = 0; t < 6; t++) {
            int comp = t >> 1;
            int q = ((t & 1) << 8) + tid;
            int row = q >> 3, cl = q & 7;
            const void* src = (comp == 0) ? (const void*)(g_kh + src0 + row * Dd + cl * 8)
                            : (comp == 1) ? (const void*)(g_kl + src0 + row * Dd + cl * 8)
                                          : (const void*)(g_vf + src0 + row * Dd + cl * 8);
            cp16(bsm + comp * 8192 + SWZ(row * 128 + cl * 16), src);
        }
    };

    // group 0 = Q tiles + kv(0); group 1 = kv(1)
    {
        const __nv_bfloat16* qs[2] = {g_qh, g_ql};
#pragma unroll
        for (int t = 0; t < 8; t++) {
            int comp = t >> 2;
            int q = ((t & 3) << 8) + tid;
            int row = q >> 3, cl = q & 7;
            cp16(smb + comp * 16384 + SWZ(row * 128 + cl * 16),
                 qs[comp] + hbase + (size_t)(r0g + row) * Dd + cl * 8);
        }
    }
    loadkv(0, 0); CP_COMMIT();
    loadkv(1, 1); CP_COMMIT();

    float oacc[8][4];
#pragma unroll
    for (int i = 0; i < 8; i++)
#pragma unroll
        for (int j = 0; j < 4; j++) oacc[i][j] = 0.f;
    float m0 = -1e30f, m1 = -1e30f, l0 = 0.f, l1 = 0.f;

    for (int c = 0; c < ntiles; c++) {
        CP_WAIT1();
        __syncthreads();
        if (c + 2 < ntiles) loadkv(c + 2, (c + 2) % 3);
        CP_COMMIT();
        const uint32_t kh = smb + 32768 + (c % 3) * 24576;
        const uint32_t kl = kh + 8192, vf = kh + 16384;

        // ---- S = Q K^T (bf16 3-term; logits in log2 domain) ----
        float sacc[8][4];
#pragma unroll
        for (int i = 0; i < 8; i++)
#pragma unroll
            for (int j = 0; j < 4; j++) sacc[i][j] = 0.f;
#pragma unroll
        for (int k16 = 0; k16 < 4; k16++) {
            const int colb = k16 * 32 + (lane >> 4) * 16;
            uint32_t ah[4], al[4];
            ldsm4(ah, smb + SWZ((wm + (lane & 15)) * 128 + colb));
            ldsm4(al, smb + 16384 + SWZ((wm + (lane & 15)) * 128 + colb));
#pragma unroll
            for (int nt4 = 0; nt4 < 4; nt4++) {
                uint32_t kh4[4], kl4[4];
                uint32_t ra = SWZ((nt4 * 16 + (lane & 15)) * 128 + colb);
                ldsm4(kh4, kh + ra);
                ldsm4(kl4, kl + ra);
                uint32_t bh0[2] = {kh4[0], kh4[2]}, bh1[2] = {kh4[1], kh4[3]};
                uint32_t bl0[2] = {kl4[0], kl4[2]}, bl1[2] = {kl4[1], kl4[3]};
                mma16816(sacc[nt4 * 2 + 0], ah, bh0);
                mma16816(sacc[nt4 * 2 + 1], ah, bh1);
                mma16816(sacc[nt4 * 2 + 0], ah, bl0);
                mma16816(sacc[nt4 * 2 + 1], ah, bl1);
                mma16816(sacc[nt4 * 2 + 0], al, bh0);
                mma16816(sacc[nt4 * 2 + 1], al, bh1);
            }
        }

        // ---- causal mask (diagonal tiles only) ----
        if (c >= 2 * rb) {
#pragma unroll
            for (int nt = 0; nt < 8; nt++) {
                const int cg = c * 64 + nt * 8 + c2;
                if (cg > row0)     sacc[nt][0] = -1e30f;
                if (cg + 1 > row0) sacc[nt][1] = -1e30f;
                if (cg > row1)     sacc[nt][2] = -1e30f;
                if (cg + 1 > row1) sacc[nt][3] = -1e30f;
            }
        }

        // ---- register softmax (quad shuffles, exp2 poly) ----
        {
            float mx0 = -1e30f, mx1 = -1e30f;
#pragma unroll
            for (int nt = 0; nt < 8; nt++) {
                mx0 = fmaxf(mx0, fmaxf(sacc[nt][0], sacc[nt][1]));
                mx1 = fmaxf(mx1, fmaxf(sacc[nt][2], sacc[nt][3]));
            }
            mx0 = fmaxf(mx0, __shfl_xor_sync(0xffffffffu, mx0, 1));
            mx0 = fmaxf(mx0, __shfl_xor_sync(0xffffffffu, mx0, 2));
            mx1 = fmaxf(mx1, __shfl_xor_sync(0xffffffffu, mx1, 1));
            mx1 = fmaxf(mx1, __shfl_xor_sync(0xffffffffu, mx1, 2));
            float mn0 = fmaxf(m0, mx0), mn1 = fmaxf(m1, mx1);
            float sc0 = exp2apx(m0 - mn0), sc1 = exp2apx(m1 - mn1);
            float s0 = 0.f, s1 = 0.f;
#pragma unroll
            for (int nt = 0; nt < 8; nt++) {
                float e0 = exp2apx(sacc[nt][0] - mn0);
                float e1 = exp2apx(sacc[nt][1] - mn0);
                float e2 = exp2apx(sacc[nt][2] - mn1);
                float e3 = exp2apx(sacc[nt][3] - mn1);
                sacc[nt][0] = e0; sacc[nt][1] = e1;
                sacc[nt][2] = e2; sacc[nt][3] = e3;
                s0 += e0 + e1; s1 += e2 + e3;
                oacc[nt][0] *= sc0; oacc[nt][1] *= sc0;
                oacc[nt][2] *= sc1; oacc[nt][3] *= sc1;
            }
            s0 += __shfl_xor_sync(0xffffffffu, s0, 1);
            s0 += __shfl_xor_sync(0xffffffffu, s0, 2);
            s1 += __shfl_xor_sync(0xffffffffu, s1, 1);
            s1 += __shfl_xor_sync(0xffffffffu, s1, 2);
            l0 = l0 * sc0 + s0; l1 = l1 * sc1 + s1;
            m0 = mn0; m1 = mn1;
        }

        // ---- O += P V (fp16 single-term) ----
#pragma unroll
        for (int kt = 0; kt < 4; kt++) {
            uint32_t ph[4] = {pkh2(sacc[2*kt][0],   sacc[2*kt][1]),
                              pkh2(sacc[2*kt][2],   sacc[2*kt][3]),
                              pkh2(sacc[2*kt+1][0], sacc[2*kt+1][1]),
                              pkh2(sacc[2*kt+1][2], sacc[2*kt+1][3])};
#pragma unroll
            for (int nt2 = 0; nt2 < 4; nt2++) {
                uint32_t ra = SWZ((kt * 16 + (lane & 15)) * 128 +
                                  nt2 * 32 + (lane >> 4) * 16);
                uint32_t v4[4];
                ldsm4t(v4, vf + ra);
                uint32_t b0[2] = {v4[0], v4[1]}, b1[2] = {v4[2], v4[3]};
                mmah(oacc[nt2 * 2 + 0], ph, b0);
                mmah(oacc[nt2 * 2 + 1], ph, b1);
            }
        }
    }

    // ---- finalize: O/l -> g_ox fp16 ----
    {
        float inv0 = 1.f / l0, inv1 = 1.f / l1;
        const size_t mg0 = (size_t)bb * Tt + row0;
#pragma unroll
        for (int nt = 0; nt < 8; nt++) {
            const int col = hh * 64 + nt * 8 + c2;
            *(uint32_t*)&g_ox[mg0 * 1024 + col] =
                pkh2(oacc[nt][0] * inv0, oacc[nt][1] * inv0);
            *(uint32_t*)&g_ox[(mg0 + 8) * 1024 + col] =
                pkh2(oacc[nt][2] * inv1, oacc[nt][3] * inv1);
        }
    }
}

// ---------------------------------------------------------------------------
extern "C" void kernel_launch(void* const* d_in, const int* in_sizes, int n_in,
                              void* d_out, int out_size) {
    const float* x  = (const float*)d_in[0];   // [2,2048,1024]
    const float* Wa = (const float*)d_in[1];   // [3072,1024]
    const float* Wp = (const float*)d_in[2];   // [1024,1024]
    float* y = (float*)d_out;                  // [2,2048,1024]

    static const int GSM = 98304;              // 3 stages x 32KB
    static const int ASM = 106496;             // Q 32KB + 3 stages x 24KB
    cudaFuncSetAttribute((const void*)gemmqk,
                         cudaFuncAttributeMaxDynamicSharedMemorySize, GSM);
    cudaFuncSetAttribute((const void*)gemmh<0>,
                         cudaFuncAttributeMaxDynamicSharedMemorySize, GSM);
    cudaFuncSetAttribute((const void*)gemmh<1>,
                         cudaFuncAttributeMaxDynamicSharedMemorySize, GSM);
    cudaFuncSetAttribute((const void*)attn_mma,
                         cudaFuncAttributeMaxDynamicSharedMemorySize, ASM);

    packall<<<8192, 256>>>(x, Wa, Wp);

    gemmqk<<<dim3(16, 32), 256, GSM>>>();              // q,k (N=2048)
    gemmh<0><<<dim3(8, 32), 256, GSM>>>(nullptr);      // v   (N=1024, fp16)

    attn_mma<<<dim3(16, 32), 256, ASM>>>();

    gemmh<1><<<dim3(8, 32), 256, GSM>>>(y);            // proj (N=1024, fp16)
}